// round 12
// baseline (speedup 1.0000x reference)
#include <cuda_runtime.h>
#include <cuda_fp16.h>
#include <stdint.h>
#include <math.h>

#define BB 4
#define LL 2048
#define KK 30
#define NHD 4
#define NLAY 3
#define NNODE (BB*LL)        /* 8192   */
#define NE (NNODE*KK)        /* 245760 */
#define EPSX 1e-6f

// ==================== device scratch (static, no allocation) ====================
__device__ float g_hV[NNODE*128];
__device__ float g_Q[NNODE*128];
__device__ __half g_wbhi[23*16384], g_wblo[23*16384];   // weights [n][k] fp16 hi/lo
__device__ __half g_updh[NNODE*128];                    // upd, fp16
__device__ uint2 g_hVh[NNODE*32];                       // hV fp16 (4 halves per uint2)
__device__ uint2 g_Vinh[NNODE*32];                      // V input fp16
__device__ uint2 g_Einh[(size_t)NE*32];                 // E input fp16
__device__ uint2 g_hEh[(size_t)NE*32];                  // hE fp16

// ==================== helpers ====================
__device__ __forceinline__ uint32_t smem_u32(const void* p) {
    uint32_t a;
    asm("{ .reg .u64 tmp; cvta.to.shared.u64 tmp, %1; cvt.u32.u64 %0, tmp; }"
        : "=r"(a) : "l"(p));
    return a;
}
__device__ __forceinline__ void ldsm4(uint32_t r[4], uint32_t addr) {
    asm volatile("ldmatrix.sync.aligned.m8n8.x4.shared.b16 {%0,%1,%2,%3}, [%4];"
        : "=r"(r[0]), "=r"(r[1]), "=r"(r[2]), "=r"(r[3]) : "r"(addr));
}
__device__ __forceinline__ void mma16816(float c[4], const uint32_t a[4], const uint32_t b[2]) {
    asm volatile("mma.sync.aligned.m16n8k16.row.col.f32.f16.f16.f32 "
        "{%0,%1,%2,%3}, {%4,%5,%6,%7}, {%8,%9}, {%0,%1,%2,%3};"
        : "+f"(c[0]), "+f"(c[1]), "+f"(c[2]), "+f"(c[3])
        : "r"(a[0]), "r"(a[1]), "r"(a[2]), "r"(a[3]), "r"(b[0]), "r"(b[1]));
}
__device__ __forceinline__ uint32_t packh2(float x, float y) {
    __half2 h = __floats2half2_rn(x, y);
    return *reinterpret_cast<uint32_t*>(&h);
}
__device__ __forceinline__ void cpa16(uint32_t dst, const void* src) {
    asm volatile("cp.async.cg.shared.global [%0], [%1], 16;" :: "r"(dst), "l"(src) : "memory");
}
#define CP_COMMIT() asm volatile("cp.async.commit_group;" ::: "memory")
#define CP_WAIT0()  asm volatile("cp.async.wait_group 0;" ::: "memory")

// ==================== smem layout ====================
#define A1B 17408                 /* 64 rows * 272B (fp16, stride 136 elems) */
#define W1B 34816                 /* 128 rows * 272B                         */
#define OFF_A  0
#define OFF_W  A1B                /* W hi @OFF_W, lo @OFF_W + W1B            */
#define SM_GEMM (A1B + 2*W1B)     /* 87040 -> 2 CTAs/SM                      */

// 128-thread stagers
__device__ __forceinline__ void stage_a_cp(uint32_t sb, const uint2* gact,
                                           const int* grow, long base, int t) {
    const uint4* g = (const uint4*)gact;   // 16B chunks, 16 per row
    #pragma unroll
    for (int i = 0; i < 8; ++i) {
        int idx = t + 128*i;               // 1024 chunks = 64 rows * 16
        int row = idx >> 4, c = idx & 15;
        long gr = grow ? (long)grow[row] : (base + row);
        uint32_t d = (uint32_t)(row*272 + c*16);
        cpa16(sb + OFF_A + d, g + gr*16 + c);
    }
}
__device__ __forceinline__ void stage_w_cp(uint32_t sb, int block, int t) {
    const uint4* sh = (const uint4*)(g_wbhi + (size_t)block*16384);
    const uint4* sl = (const uint4*)(g_wblo + (size_t)block*16384);
    #pragma unroll
    for (int i = 0; i < 16; ++i) {
        int idx = t + 128*i;               // 2048 chunks = 128 rows * 16
        int row = idx >> 4, c = idx & 15;
        uint32_t d = (uint32_t)(row*272 + c*16);
        cpa16(sb + OFF_W + d,       sh + idx);
        cpa16(sb + OFF_W + W1B + d, sl + idx);
    }
}

// 2-term split GEMM on 64x128 tile; 4 warps, warp tile 32x64.
// acc += Ah @ (Wh + Wl)^T
__device__ __forceinline__ void gemm2(uint32_t sb, int lane, int wr, int wc,
                                      float acc[2][8][4]) {
    uint32_t arow = (uint32_t)(32*wr + (lane & 15));
    uint32_t acol = (uint32_t)((lane >> 4) << 3);
    uint32_t brow = (uint32_t)(64*wc + (lane & 7) + ((lane >> 4) << 3));
    uint32_t bcol = (uint32_t)(((lane >> 3) & 1) << 3);
    #pragma unroll 2
    for (int ks = 0; ks < 8; ++ks) {
        uint32_t k0 = (uint32_t)(ks*16);
        uint32_t ah[2][4];
        #pragma unroll
        for (int mi = 0; mi < 2; ++mi) {
            uint32_t off = ((arow + 16u*mi)*136u + k0 + acol)*2u;
            ldsm4(ah[mi], sb + OFF_A + off);
        }
        uint32_t bh[8][2], bl[8][2];
        #pragma unroll
        for (int jp = 0; jp < 4; ++jp) {
            uint32_t off = ((brow + 16u*jp)*136u + k0 + bcol)*2u;
            uint32_t r[4];
            ldsm4(r, sb + OFF_W + off);
            bh[2*jp][0] = r[0]; bh[2*jp][1] = r[1];
            bh[2*jp+1][0] = r[2]; bh[2*jp+1][1] = r[3];
            ldsm4(r, sb + OFF_W + W1B + off);
            bl[2*jp][0] = r[0]; bl[2*jp][1] = r[1];
            bl[2*jp+1][0] = r[2]; bl[2*jp+1][1] = r[3];
        }
        #pragma unroll
        for (int mi = 0; mi < 2; ++mi)
            #pragma unroll
            for (int j = 0; j < 8; ++j) {
                mma16816(acc[mi][j], ah[mi], bh[j]);
                mma16816(acc[mi][j], ah[mi], bl[j]);
            }
    }
}

// ==================== conversion kernels ====================
// blocks: 0 Ws, 1 Wt, 2-4 Wq, 5-7 Wk1, 8-10 Wk2, 11-16 Wv, 17-19 fc1, 20-22 Wo
__global__ void k_wconv_all(const float* __restrict__ Ws, const float* __restrict__ Wt,
                            const float* __restrict__ Wq, const float* __restrict__ Wk1,
                            const float* __restrict__ Wk2, const float* __restrict__ Wv,
                            const float* __restrict__ fc1, const float* __restrict__ Wo) {
    int i = blockIdx.x*blockDim.x + threadIdx.x;
    if (i >= 23*16384) return;
    int blk = i >> 14, r = i & 16383, n = r >> 7, k = r & 127;
    const float* src; int sub;
    if (blk == 0)       { src = Ws;  sub = 0; }
    else if (blk == 1)  { src = Wt;  sub = 0; }
    else if (blk < 5)   { src = Wq;  sub = blk - 2; }
    else if (blk < 8)   { src = Wk1; sub = blk - 5; }
    else if (blk < 11)  { src = Wk2; sub = blk - 8; }
    else if (blk < 17)  { src = Wv;  sub = blk - 11; }
    else if (blk < 20)  { src = fc1; sub = blk - 17; }
    else                { src = Wo;  sub = blk - 20; }
    float v = src[(size_t)sub*16384 + k*128 + n];
    __half h = __float2half_rn(v);
    __half l = __float2half_rn(v - __half2float(h));
    size_t e = (size_t)blk*16384 + n*128 + k;
    g_wbhi[e] = h; g_wblo[e] = l;
}

__global__ void k_fconv_all(const float* __restrict__ V, const float* __restrict__ E,
                            uint2* __restrict__ vh, uint2* __restrict__ eh) {
    int i = blockIdx.x*blockDim.x + threadIdx.x;
    int nv = NNODE*32;
    if (i < nv) {
        float4 v = ((const float4*)V)[i];
        vh[i] = make_uint2(packh2(v.x, v.y), packh2(v.z, v.w));
    } else {
        long j = (long)i - nv;
        if (j >= (long)NE*32) return;
        float4 v = ((const float4*)E)[j];
        eh[j] = make_uint2(packh2(v.x, v.y), packh2(v.z, v.w));
    }
}

// ==================== k_proj: out = A @ W^T (+bias). 64 rows/CTA ====
__global__ __launch_bounds__(128, 2) void k_proj(const uint2* __restrict__ act,
                                                 int wblock,
                                                 const float* __restrict__ bias,
                                                 float* __restrict__ outf,
                                                 __half* __restrict__ outh) {
    extern __shared__ char smc[];
    uint32_t sb = smem_u32(smc);
    int t = threadIdx.x, lane = t & 31, wid = t >> 5, wr = wid & 1, wc = wid >> 1;
    long base = (long)blockIdx.x*64;

    stage_w_cp(sb, wblock, t);
    stage_a_cp(sb, act, nullptr, base, t);
    CP_COMMIT(); CP_WAIT0();
    __syncthreads();
    float acc[2][8][4] = {};
    gemm2(sb, lane, wr, wc, acc);

    #pragma unroll
    for (int mi = 0; mi < 2; ++mi)
        #pragma unroll
        for (int hh = 0; hh < 2; ++hh) {
            long row = base + 32*wr + 16*mi + 8*hh + (lane >> 2);
            #pragma unroll
            for (int j = 0; j < 8; ++j) {
                int col = 64*wc + 8*j + 2*(lane & 3);
                float x = acc[mi][j][2*hh], y = acc[mi][j][2*hh + 1];
                if (bias) { x += bias[col]; y += bias[col + 1]; }
                if (outf) *(float2*)(outf + row*128 + col) = make_float2(x, y);
                if (outh) *(uint32_t*)(outh + row*128 + col) = packh2(x, y);
            }
        }
}

// ==================== k_lv: fused K1/K2/logits/softmax/Vh/upd ====================
// CTA = 60 edge rows = 2 complete nodes (padded to 64). Grid = NE/60 = 4096.
__global__ __launch_bounds__(128, 2) void k_lv(const int* __restrict__ E_idx,
                                               const float* __restrict__ mask,
                                               int bk1, int bk2, int bv0, int bv1) {
    extern __shared__ char smc[];
    __shared__ int growE[64], growG[64];
    __shared__ float att_s[240];      // [r*4 + head], r < 60
    uint32_t sb = smem_u32(smc);
    int t = threadIdx.x, lane = t & 31, wid = t >> 5, wr = wid & 1, wc = wid >> 1;
    long base = (long)blockIdx.x*60;
    int node0 = blockIdx.x*2;

    if (t < 64) {
        long e = base + ((t < 60) ? t : 59);   // clamp padding rows
        growE[t] = (int)e;
        growG[t] = (int)(e/(LL*KK))*LL + E_idx[e];
    }
    __syncthreads();
    stage_a_cp(sb, g_hEh, growE, 0, t);
    stage_w_cp(sb, bk1, t);
    CP_COMMIT(); CP_WAIT0();
    __syncthreads();

    float acc1[2][8][4] = {};
    gemm2(sb, lane, wr, wc, acc1);                 // K1 = hE @ Wk1
    __syncthreads();

    stage_a_cp(sb, g_hVh, growG, 0, t);            // A <- gathered hV
    stage_w_cp(sb, bk2, t);
    CP_COMMIT(); CP_WAIT0();
    __syncthreads();

    float acc2[2][8][4] = {};
    gemm2(sb, lane, wr, wc, acc2);                 // K2 = hKV @ Wk2

    // raw logits -> att_s  (acc1, acc2 dead afterwards)
    #pragma unroll
    for (int mi = 0; mi < 2; ++mi)
        #pragma unroll
        for (int hh = 0; hh < 2; ++hh) {
            int r = 32*wr + 16*mi + 8*hh + (lane >> 2);
            int node = growE[r] / KK;
            const float* qrow = g_Q + (size_t)node*128;
            float s0 = 0.f, s1 = 0.f;
            #pragma unroll
            for (int j = 0; j < 8; ++j) {
                int col = 64*wc + 8*j + 2*(lane & 3);
                float2 q = *(const float2*)(qrow + col);
                float p = q.x*acc1[mi][j][2*hh]  *acc2[mi][j][2*hh]
                        + q.y*acc1[mi][j][2*hh+1]*acc2[mi][j][2*hh+1];
                if (j < 4) s0 += p; else s1 += p;
            }
            s0 += __shfl_xor_sync(0xffffffffu, s0, 1);
            s0 += __shfl_xor_sync(0xffffffffu, s0, 2);
            s1 += __shfl_xor_sync(0xffffffffu, s1, 1);
            s1 += __shfl_xor_sync(0xffffffffu, s1, 2);
            if ((lane & 3) == 0 && r < 60) {
                att_s[r*4 + 2*wc    ] = s0*(1.f/32.f);
                att_s[r*4 + 2*wc + 1] = s1*(1.f/32.f);
            }
        }
    __syncthreads();

    // masked softmax per (node_l, head): 8 threads, 3 smem passes
    // matches reference: attend = m * softmax(where(m>0, logits, -inf))
    if (t < 8) {
        int nl = t >> 2, h = t & 3;
        int ng = node0 + nl;
        int b = ng / LL;
        float msel = mask[ng];
        const int* eidx = &E_idx[(size_t)ng*KK];
        float mx = -3.4e38f;
        for (int k = 0; k < KK; ++k) {
            float mk = msel*mask[b*LL + eidx[k]];
            float v = att_s[(nl*KK + k)*4 + h];
            if (mk > 0.f && v > mx) mx = v;
        }
        float s = 0.f;
        for (int k = 0; k < KK; ++k) {
            float mk = msel*mask[b*LL + eidx[k]];
            float e = (mk > 0.f) ? __expf(att_s[(nl*KK + k)*4 + h] - mx) : 0.f;
            att_s[(nl*KK + k)*4 + h] = mk*e;
            s += e;
        }
        float inv = (s > 0.f) ? (1.f/s) : 0.f;
        for (int k = 0; k < KK; ++k)
            att_s[(nl*KK + k)*4 + h] *= inv;
    }
    __syncthreads();

    stage_w_cp(sb, bv1, t);                        // A stays hKV
    CP_COMMIT(); CP_WAIT0();
    __syncthreads();
    float accv[2][8][4] = {};
    gemm2(sb, lane, wr, wc, accv);                 // Vh = hKV @ Wv1
    __syncthreads();

    stage_a_cp(sb, g_hEh, growE, 0, t);            // restage hE
    stage_w_cp(sb, bv0, t);
    CP_COMMIT(); CP_WAIT0();
    __syncthreads();
    gemm2(sb, lane, wr, wc, accv);                 // Vh += hE @ Wv0
    __syncthreads();                               // all ldsm done; smem reusable

    // attend-scaled Vh -> smem, stride 132 floats
    float* up = (float*)smc;
    #pragma unroll
    for (int mi = 0; mi < 2; ++mi)
        #pragma unroll
        for (int hh = 0; hh < 2; ++hh) {
            int r = 32*wr + 16*mi + 8*hh + (lane >> 2);
            if (r < 60) {
                float a0 = att_s[r*4 + 2*wc];
                float a1 = att_s[r*4 + 2*wc + 1];
                #pragma unroll
                for (int j = 0; j < 8; ++j) {
                    int col = 64*wc + 8*j + 2*(lane & 3);
                    float a = (j < 4) ? a0 : a1;
                    *(float2*)(up + r*132 + col) =
                        make_float2(a*accv[mi][j][2*hh], a*accv[mi][j][2*hh+1]);
                }
            }
        }
    __syncthreads();

    // reduce 30 edges per node -> upd, write fp16
    {
        int nl = t >> 6, cp = t & 63;
        float sx = 0.f, sy = 0.f;
        #pragma unroll
        for (int e = 0; e < KK; ++e) {
            float2 v = *(const float2*)(up + (nl*KK + e)*132 + 2*cp);
            sx += v.x; sy += v.y;
        }
        long ng = node0 + nl;
        *(uint32_t*)(g_updh + ng*128 + 2*cp) = packh2(sx, sy);
    }
}

// ==================== k_attn2: h_V = mask * LN(h_V + upd@Wo) ====================
__global__ __launch_bounds__(128, 2) void k_attn2(int wblock,
                                                  const float* __restrict__ mask,
                                                  const float* __restrict__ lng,
                                                  const float* __restrict__ lnb) {
    extern __shared__ char smc[];
    __shared__ float reds[128], reds2[128];
    uint32_t sb = smem_u32(smc);
    int t = threadIdx.x, lane = t & 31, wid = t >> 5, wr = wid & 1, wc = wid >> 1;
    long base = (long)blockIdx.x*64;

    stage_w_cp(sb, wblock, t);
    stage_a_cp(sb, (const uint2*)g_updh, nullptr, base, t);
    CP_COMMIT(); CP_WAIT0();
    __syncthreads();
    float acc[2][8][4] = {};
    gemm2(sb, lane, wr, wc, acc);

    #pragma unroll
    for (int mi = 0; mi < 2; ++mi)
        #pragma unroll
        for (int hh = 0; hh < 2; ++hh) {
            int r = 32*wr + 16*mi + 8*hh + (lane >> 2);
            long row = base + r;
            float s = 0.f, s2 = 0.f;
            #pragma unroll
            for (int j = 0; j < 8; ++j) {
                int col = 64*wc + 8*j + 2*(lane & 3);
                float2 hv = *(const float2*)(g_hV + row*128 + col);
                float x = hv.x + acc[mi][j][2*hh];
                float y = hv.y + acc[mi][j][2*hh+1];
                acc[mi][j][2*hh] = x; acc[mi][j][2*hh+1] = y;
                s += x + y; s2 += x*x + y*y;
            }
            s  += __shfl_xor_sync(0xffffffffu, s, 1);
            s  += __shfl_xor_sync(0xffffffffu, s, 2);
            s2 += __shfl_xor_sync(0xffffffffu, s2, 1);
            s2 += __shfl_xor_sync(0xffffffffu, s2, 2);
            if ((lane & 3) == 0) { reds[r*2 + wc] = s; reds2[r*2 + wc] = s2; }
        }
    __syncthreads();

    #pragma unroll
    for (int mi = 0; mi < 2; ++mi)
        #pragma unroll
        for (int hh = 0; hh < 2; ++hh) {
            int r = 32*wr + 16*mi + 8*hh + (lane >> 2);
            long row = base + r;
            float s  = reds[r*2] + reds[r*2 + 1];
            float s2 = reds2[r*2] + reds2[r*2 + 1];
            float mu  = s*(1.f/128.f);
            float var = fmaxf((s2 - 128.f*mu*mu)*(1.f/127.f), 0.f);
            float rs  = 1.f/(sqrtf(var + EPSX) + EPSX);
            float m   = mask[row];
            #pragma unroll
            for (int j = 0; j < 8; ++j) {
                int col = 64*wc + 8*j + 2*(lane & 3);
                float x = m*(lng[col    ]*(acc[mi][j][2*hh]   - mu)*rs + lnb[col]);
                float y = m*(lng[col + 1]*(acc[mi][j][2*hh+1] - mu)*rs + lnb[col + 1]);
                *(float2*)(g_hV + row*128 + col) = make_float2(x, y);
                *(uint32_t*)((__half*)g_hVh + row*128 + col) = packh2(x, y);
            }
        }
}

// ==================== k_fc1: h_E = LN(relu([hE, hKV, hVself] @ fc1 + b)) ====
__global__ __launch_bounds__(128, 2) void k_fc1(const int* __restrict__ E_idx,
                                                const float* __restrict__ fc1b,
                                                const float* __restrict__ ng,
                                                const float* __restrict__ nb) {
    extern __shared__ char smc[];
    __shared__ int grow[64], grow2[64];
    __shared__ float reds[128], reds2[128];
    uint32_t sb = smem_u32(smc);
    int t = threadIdx.x, lane = t & 31, wid = t >> 5, wr = wid & 1, wc = wid >> 1;
    long base = (long)blockIdx.x*64;

    if (t < 64) {
        long e = base + t;
        grow[t]  = (int)(e/(LL*KK))*LL + E_idx[e];
        grow2[t] = (int)(e / KK);
    }
    stage_a_cp(sb, g_hEh, nullptr, base, t);
    stage_w_cp(sb, 17, t);
    CP_COMMIT(); CP_WAIT0();
    __syncthreads();

    float acc[2][8][4] = {};
    gemm2(sb, lane, wr, wc, acc);
    __syncthreads();

    stage_a_cp(sb, g_hVh, grow, 0, t);
    stage_w_cp(sb, 18, t);
    CP_COMMIT(); CP_WAIT0();
    __syncthreads();

    gemm2(sb, lane, wr, wc, acc);
    __syncthreads();

    stage_a_cp(sb, g_hVh, grow2, 0, t);
    stage_w_cp(sb, 19, t);
    CP_COMMIT(); CP_WAIT0();
    __syncthreads();

    gemm2(sb, lane, wr, wc, acc);

    #pragma unroll
    for (int mi = 0; mi < 2; ++mi)
        #pragma unroll
        for (int hh = 0; hh < 2; ++hh) {
            int r = 32*wr + 16*mi + 8*hh + (lane >> 2);
            float s = 0.f, s2 = 0.f;
            #pragma unroll
            for (int j = 0; j < 8; ++j) {
                int col = 64*wc + 8*j + 2*(lane & 3);
                float x = fmaxf(acc[mi][j][2*hh]   + fc1b[col],     0.f);
                float y = fmaxf(acc[mi][j][2*hh+1] + fc1b[col + 1], 0.f);
                acc[mi][j][2*hh] = x; acc[mi][j][2*hh+1] = y;
                s += x + y; s2 += x*x + y*y;
            }
            s  += __shfl_xor_sync(0xffffffffu, s, 1);
            s  += __shfl_xor_sync(0xffffffffu, s, 2);
            s2 += __shfl_xor_sync(0xffffffffu, s2, 1);
            s2 += __shfl_xor_sync(0xffffffffu, s2, 2);
            if ((lane & 3) == 0) { reds[r*2 + wc] = s; reds2[r*2 + wc] = s2; }
        }
    __syncthreads();

    #pragma unroll
    for (int mi = 0; mi < 2; ++mi)
        #pragma unroll
        for (int hh = 0; hh < 2; ++hh) {
            int r = 32*wr + 16*mi + 8*hh + (lane >> 2);
            float s  = reds[r*2] + reds[r*2 + 1];
            float s2 = reds2[r*2] + reds2[r*2 + 1];
            float mu  = s*(1.f/128.f);
            float var = fmaxf((s2 - 128.f*mu*mu)*(1.f/127.f), 0.f);
            float rs  = 1.f/(sqrtf(var + EPSX) + EPSX);
            long row = base + r;
            #pragma unroll
            for (int j = 0; j < 8; ++j) {
                int col = 64*wc + 8*j + 2*(lane & 3);
                float x = ng[col    ]*(acc[mi][j][2*hh]   - mu)*rs + nb[col];
                float y = ng[col + 1]*(acc[mi][j][2*hh+1] - mu)*rs + nb[col + 1];
                *(uint32_t*)((__half*)g_hEh + (size_t)row*128 + col) = packh2(x, y);
            }
        }
}

__global__ void k_copy(float* __restrict__ out) {
    int i = blockIdx.x*blockDim.x + threadIdx.x;
    reinterpret_cast<float4*>(out)[i] = reinterpret_cast<const float4*>(g_hV)[i];
}

// =========================================================================
extern "C" void kernel_launch(void* const* d_in, const int* in_sizes, int n_in,
                              void* d_out, int out_size) {
    const float* V      = (const float*)d_in[0];
    const float* E      = (const float*)d_in[1];
    const int*   E_idx  = (const int*)  d_in[2];
    const float* mask   = (const float*)d_in[3];
    const float* Ws_w   = (const float*)d_in[4];
    const float* Ws_b   = (const float*)d_in[5];
    const float* Wt_w   = (const float*)d_in[6];
    const float* Wt_b   = (const float*)d_in[7];
    const float* Wq     = (const float*)d_in[8];
    const float* Wk1    = (const float*)d_in[9];
    const float* Wk2    = (const float*)d_in[10];
    const float* Wv     = (const float*)d_in[11];
    const float* Wo     = (const float*)d_in[12];
    const float* ln_g   = (const float*)d_in[13];
    const float* ln_b   = (const float*)d_in[14];
    const float* fc1_w  = (const float*)d_in[15];
    const float* fc1_b  = (const float*)d_in[16];
    const float* norm_g = (const float*)d_in[17];
    const float* norm_b = (const float*)d_in[18];

    cudaFuncSetAttribute(k_proj,  cudaFuncAttributeMaxDynamicSharedMemorySize, SM_GEMM);
    cudaFuncSetAttribute(k_lv,    cudaFuncAttributeMaxDynamicSharedMemorySize, SM_GEMM);
    cudaFuncSetAttribute(k_attn2, cudaFuncAttributeMaxDynamicSharedMemorySize, SM_GEMM);
    cudaFuncSetAttribute(k_fc1,   cudaFuncAttributeMaxDynamicSharedMemorySize, SM_GEMM);

    void *phV, *pQ, *pVinh, *pEinh, *phVh, *phEh;
    cudaGetSymbolAddress(&phV,  g_hV);
    cudaGetSymbolAddress(&pQ,   g_Q);
    cudaGetSymbolAddress(&pVinh, g_Vinh);
    cudaGetSymbolAddress(&pEinh, g_Einh);
    cudaGetSymbolAddress(&phVh, g_hVh);
    cudaGetSymbolAddress(&phEh, g_hEh);

    k_wconv_all<<<(23*16384 + 255)/256, 256>>>(Ws_w, Wt_w, Wq, Wk1, Wk2, Wv, fc1_w, Wo);
    k_fconv_all<<<((NNODE + NE)*32 + 255)/256, 256>>>(V, E, (uint2*)pVinh, (uint2*)pEinh);
    k_proj<<<NNODE/64, 128, SM_GEMM>>>((const uint2*)pVinh, 0, Ws_b,
                                       (float*)phV, (__half*)phVh);
    k_proj<<<NE/64, 128, SM_GEMM>>>((const uint2*)pEinh, 1, Wt_b,
                                    nullptr, (__half*)phEh);

    for (int i = 0; i < NLAY; ++i) {
        k_proj<<<NNODE/64, 128, SM_GEMM>>>((const uint2*)phVh, 2 + i, nullptr,
                                           (float*)pQ, nullptr);
        k_lv<<<NE/60, 128, SM_GEMM>>>(E_idx, mask, 5 + i, 8 + i, 11 + 2*i, 12 + 2*i);
        k_attn2<<<NNODE/64, 128, SM_GEMM>>>(20 + i, mask, ln_g + i*128, ln_b + i*128);
        k_fc1<<<NE/64, 128, SM_GEMM>>>(E_idx, fc1_b, norm_g, norm_b);
    }

    k_copy<<<(NNODE*128/4)/256, 256>>>((float*)d_out);
    (void)in_sizes; (void)n_in; (void)out_size;
}

// round 13
// speedup vs baseline: 1.2183x; 1.2183x over previous
#include <cuda_runtime.h>
#include <cuda_bf16.h>
#include <stdint.h>
#include <math.h>

#define BB 4
#define LL 2048
#define KK 30
#define NHD 4
#define NLAY 3
#define NNODE (BB*LL)        /* 8192   */
#define NE (NNODE*KK)        /* 245760 */
#define EPSX 1e-6f

// ==================== device scratch (static, no allocation) ====================
__device__ float g_hV[NNODE*128];
__device__ float g_Q[NNODE*128];
__device__ float g_Vh[(size_t)NE*128];
__device__ float g_logits[(size_t)NNODE*NHD*KK];
__device__ __nv_bfloat16 g_wbhi[23*16384], g_wblo[23*16384];   // weights [n][k] bf16
__device__ uint4 g_hVhi[NNODE*16], g_hVlo[NNODE*16];
__device__ uint4 g_Vinhi[NNODE*16], g_Vinlo[NNODE*16];
__device__ uint4 g_Einhi[(size_t)NE*16], g_Einlo[(size_t)NE*16];
__device__ uint4 g_hEhi[(size_t)NE*16],  g_hElo[(size_t)NE*16];

// ==================== helpers ====================
__device__ __forceinline__ uint32_t smem_u32(const void* p) {
    uint32_t a;
    asm("{ .reg .u64 tmp; cvta.to.shared.u64 tmp, %1; cvt.u32.u64 %0, tmp; }"
        : "=r"(a) : "l"(p));
    return a;
}
__device__ __forceinline__ void ldsm4(uint32_t r[4], uint32_t addr) {
    asm volatile("ldmatrix.sync.aligned.m8n8.x4.shared.b16 {%0,%1,%2,%3}, [%4];"
        : "=r"(r[0]), "=r"(r[1]), "=r"(r[2]), "=r"(r[3]) : "r"(addr));
}
__device__ __forceinline__ void mma16816(float c[4], const uint32_t a[4], const uint32_t b[2]) {
    asm volatile("mma.sync.aligned.m16n8k16.row.col.f32.bf16.bf16.f32 "
        "{%0,%1,%2,%3}, {%4,%5,%6,%7}, {%8,%9}, {%0,%1,%2,%3};"
        : "+f"(c[0]), "+f"(c[1]), "+f"(c[2]), "+f"(c[3])
        : "r"(a[0]), "r"(a[1]), "r"(a[2]), "r"(a[3]), "r"(b[0]), "r"(b[1]));
}
__device__ __forceinline__ void hilo2(float x, float y, uint32_t& h, uint32_t& l) {
    __nv_bfloat16 hx = __float2bfloat16_rn(x), hy = __float2bfloat16_rn(y);
    __nv_bfloat16 lx = __float2bfloat16_rn(x - __bfloat162float(hx));
    __nv_bfloat16 ly = __float2bfloat16_rn(y - __bfloat162float(hy));
    h = (uint32_t)__bfloat16_as_ushort(hx) | ((uint32_t)__bfloat16_as_ushort(hy) << 16);
    l = (uint32_t)__bfloat16_as_ushort(lx) | ((uint32_t)__bfloat16_as_ushort(ly) << 16);
}
__device__ __forceinline__ void hilo4(float4 v, uint2& h, uint2& l) {
    hilo2(v.x, v.y, h.x, l.x);
    hilo2(v.z, v.w, h.y, l.y);
}
__device__ __forceinline__ void cpa16(uint32_t dst, const void* src) {
    asm volatile("cp.async.cg.shared.global [%0], [%1], 16;" :: "r"(dst), "l"(src) : "memory");
}
#define CP_COMMIT() asm volatile("cp.async.commit_group;" ::: "memory")
#define CP_WAIT0()  asm volatile("cp.async.wait_group 0;" ::: "memory")

// ==================== smem layout ====================
#define A1B 17408                 /* 64*272                 */
#define W1B 34816                 /* 128*272                */
#define OFF_A  0                  /* A hi @0, A lo @A1B     */
#define OFF_W  (2*A1B)            /* W hi @OFF_W, lo +W1B   */
#define SM_GEMM (2*A1B + 2*W1B)   /* 104448 -> 2 CTAs/SM    */

// 128-thread stagers
__device__ __forceinline__ void stage_a_cp(uint32_t sb, const uint4* ghi,
                                           const uint4* glo, const int* grow,
                                           long base, int t) {
    #pragma unroll
    for (int i = 0; i < 8; ++i) {
        int idx = t + 128*i;              // 1024 chunks = 64 rows * 16
        int row = idx >> 4, c = idx & 15;
        long gr = grow ? (long)grow[row] : (base + row);
        uint32_t d = (uint32_t)(row*272 + c*16);
        cpa16(sb + OFF_A + d,       ghi + gr*16 + c);
        cpa16(sb + OFF_A + A1B + d, glo + gr*16 + c);
    }
}
__device__ __forceinline__ void stage_w_cp(uint32_t sb, int block, int t) {
    const uint4* sh = (const uint4*)(g_wbhi + (size_t)block*16384);
    const uint4* sl = (const uint4*)(g_wblo + (size_t)block*16384);
    #pragma unroll
    for (int i = 0; i < 16; ++i) {
        int idx = t + 128*i;              // 2048 chunks = 128 rows * 16
        int row = idx >> 4, c = idx & 15;
        uint32_t d = (uint32_t)(row*272 + c*16);
        cpa16(sb + OFF_W + d,       sh + idx);
        cpa16(sb + OFF_W + W1B + d, sl + idx);
    }
}

// 3-term split GEMM on 64x128 tile; 4 warps, warp tile 32x64.
__device__ __forceinline__ void gemm3(uint32_t sb, int lane, int wr, int wc,
                                      float acc[2][8][4]) {
    uint32_t arow = (uint32_t)(32*wr + (lane & 15));
    uint32_t acol = (uint32_t)((lane >> 4) << 3);
    uint32_t brow = (uint32_t)(64*wc + (lane & 7) + ((lane >> 4) << 3));
    uint32_t bcol = (uint32_t)(((lane >> 3) & 1) << 3);
    #pragma unroll 2
    for (int ks = 0; ks < 8; ++ks) {
        uint32_t k0 = (uint32_t)(ks*16);
        uint32_t ah[2][4], al[2][4];
        #pragma unroll
        for (int mi = 0; mi < 2; ++mi) {
            uint32_t off = ((arow + 16u*mi)*136u + k0 + acol)*2u;
            ldsm4(ah[mi], sb + OFF_A + off);
            ldsm4(al[mi], sb + OFF_A + A1B + off);
        }
        uint32_t bh[8][2], bl[8][2];
        #pragma unroll
        for (int jp = 0; jp < 4; ++jp) {
            uint32_t off = ((brow + 16u*jp)*136u + k0 + bcol)*2u;
            uint32_t r[4];
            ldsm4(r, sb + OFF_W + off);
            bh[2*jp][0] = r[0]; bh[2*jp][1] = r[1];
            bh[2*jp+1][0] = r[2]; bh[2*jp+1][1] = r[3];
            ldsm4(r, sb + OFF_W + W1B + off);
            bl[2*jp][0] = r[0]; bl[2*jp][1] = r[1];
            bl[2*jp+1][0] = r[2]; bl[2*jp+1][1] = r[3];
        }
        #pragma unroll
        for (int mi = 0; mi < 2; ++mi)
            #pragma unroll
            for (int j = 0; j < 8; ++j) {
                mma16816(acc[mi][j], ah[mi], bh[j]);
                mma16816(acc[mi][j], ah[mi], bl[j]);
                mma16816(acc[mi][j], al[mi], bh[j]);
            }
    }
}

// ==================== conversion kernels ====================
// blocks: 0 Ws, 1 Wt, 2-4 Wq, 5-7 Wk1, 8-10 Wk2, 11-16 Wv, 17-19 fc1, 20-22 Wo
__global__ void k_wconv_all(const float* __restrict__ Ws, const float* __restrict__ Wt,
                            const float* __restrict__ Wq, const float* __restrict__ Wk1,
                            const float* __restrict__ Wk2, const float* __restrict__ Wv,
                            const float* __restrict__ fc1, const float* __restrict__ Wo) {
    int i = blockIdx.x*blockDim.x + threadIdx.x;
    if (i >= 23*16384) return;
    int blk = i >> 14, r = i & 16383, n = r >> 7, k = r & 127;
    const float* src; int sub;
    if (blk == 0)       { src = Ws;  sub = 0; }
    else if (blk == 1)  { src = Wt;  sub = 0; }
    else if (blk < 5)   { src = Wq;  sub = blk - 2; }
    else if (blk < 8)   { src = Wk1; sub = blk - 5; }
    else if (blk < 11)  { src = Wk2; sub = blk - 8; }
    else if (blk < 17)  { src = Wv;  sub = blk - 11; }
    else if (blk < 20)  { src = fc1; sub = blk - 17; }
    else                { src = Wo;  sub = blk - 20; }
    float v = src[(size_t)sub*16384 + k*128 + n];
    __nv_bfloat16 h = __float2bfloat16_rn(v);
    __nv_bfloat16 l = __float2bfloat16_rn(v - __bfloat162float(h));
    size_t e = (size_t)blk*16384 + n*128 + k;
    g_wbhi[e] = h; g_wblo[e] = l;
}

__global__ void k_fconv_all(const float* __restrict__ V, const float* __restrict__ E,
                            uint2* __restrict__ vhi, uint2* __restrict__ vlo,
                            uint2* __restrict__ ehi, uint2* __restrict__ elo) {
    int i = blockIdx.x*blockDim.x + threadIdx.x;
    int nv = NNODE*32;
    if (i < nv) {
        float4 v = ((const float4*)V)[i];
        uint2 h, l; hilo4(v, h, l);
        vhi[i] = h; vlo[i] = l;
    } else {
        long j = (long)i - nv;
        if (j >= (long)NE*32) return;
        float4 v = ((const float4*)E)[j];
        uint2 h, l; hilo4(v, h, l);
        ehi[j] = h; elo[j] = l;
    }
}

// ==================== k_proj: PERSISTENT. out = A @ W^T (+bias) ====
// Each CTA stages W once, loops over row-tiles; next A staged under epilogue.
__global__ __launch_bounds__(128, 2) void k_proj(const uint4* __restrict__ ahi,
                                                 const uint4* __restrict__ alo,
                                                 int wblock,
                                                 const float* __restrict__ bias,
                                                 float* __restrict__ outf,
                                                 __nv_bfloat16* __restrict__ outhi,
                                                 __nv_bfloat16* __restrict__ outlo,
                                                 int ntiles) {
    extern __shared__ char smc[];
    uint32_t sb = smem_u32(smc);
    int t = threadIdx.x, lane = t & 31, wid = t >> 5, wr = wid & 1, wc = wid >> 1;

    stage_w_cp(sb, wblock, t);
    int tile = blockIdx.x;
    if (tile < ntiles)
        stage_a_cp(sb, ahi, alo, nullptr, (long)tile*64, t);
    CP_COMMIT(); CP_WAIT0();
    __syncthreads();

    for (; tile < ntiles; tile += gridDim.x) {
        float acc[2][8][4] = {};
        gemm3(sb, lane, wr, wc, acc);
        __syncthreads();                      // all warps done reading A

        int nxt = tile + gridDim.x;
        if (nxt < ntiles) {
            stage_a_cp(sb, ahi, alo, nullptr, (long)nxt*64, t);
            CP_COMMIT();
        }

        long base = (long)tile*64;
        #pragma unroll
        for (int mi = 0; mi < 2; ++mi)
            #pragma unroll
            for (int hh = 0; hh < 2; ++hh) {
                long row = base + 32*wr + 16*mi + 8*hh + (lane >> 2);
                #pragma unroll
                for (int j = 0; j < 8; ++j) {
                    int col = 64*wc + 8*j + 2*(lane & 3);
                    float x = acc[mi][j][2*hh], y = acc[mi][j][2*hh + 1];
                    if (bias) { x += bias[col]; y += bias[col + 1]; }
                    if (outf) *(float2*)(outf + row*128 + col) = make_float2(x, y);
                    if (outhi) {
                        uint32_t h, l; hilo2(x, y, h, l);
                        *(uint32_t*)(outhi + row*128 + col) = h;
                        *(uint32_t*)(outlo + row*128 + col) = l;
                    }
                }
            }
        CP_WAIT0(); __syncthreads();
    }
}

// ==================== k_lv: K1, K2 -> logits; Vh. 64 rows/CTA ====================
__global__ __launch_bounds__(128, 2) void k_lv(const int* __restrict__ E_idx,
                                               int bk1, int bk2, int bv0, int bv1) {
    extern __shared__ char smc[];
    __shared__ int grow[64];
    uint32_t sb = smem_u32(smc);
    int t = threadIdx.x, lane = t & 31, wid = t >> 5, wr = wid & 1, wc = wid >> 1;
    long base = (long)blockIdx.x*64;

    if (t < 64) {
        long e = base + t;
        grow[t] = (int)(e/(LL*KK))*LL + E_idx[e];
    }
    stage_a_cp(sb, g_hEhi, g_hElo, nullptr, base, t);
    stage_w_cp(sb, bk1, t);
    CP_COMMIT(); CP_WAIT0();
    __syncthreads();                               // grow visible too

    float acc1[2][8][4] = {};
    gemm3(sb, lane, wr, wc, acc1);                 // K1 = hE @ Wk1
    __syncthreads();

    stage_a_cp(sb, g_hVhi, g_hVlo, grow, 0, t);    // A <- gathered hV
    stage_w_cp(sb, bk2, t);
    CP_COMMIT(); CP_WAIT0();
    __syncthreads();

    float acc2[2][8][4] = {};
    gemm3(sb, lane, wr, wc, acc2);                 // K2 = hKV @ Wk2
    __syncthreads();

    // overlap: start Wv1 load, then do logits epilogue, then wait
    stage_w_cp(sb, bv1, t);
    CP_COMMIT();

    #pragma unroll
    for (int mi = 0; mi < 2; ++mi)
        #pragma unroll
        for (int hh = 0; hh < 2; ++hh) {
            int r = 32*wr + 16*mi + 8*hh + (lane >> 2);
            long e = base + r;
            int node = (int)(e / KK), kk = (int)(e - (long)node*KK);
            const float* qrow = g_Q + (size_t)node*128;
            float s0 = 0.f, s1 = 0.f;
            #pragma unroll
            for (int j = 0; j < 8; ++j) {
                int col = 64*wc + 8*j + 2*(lane & 3);
                float2 q = *(const float2*)(qrow + col);
                float p = q.x*acc1[mi][j][2*hh]  *acc2[mi][j][2*hh]
                        + q.y*acc1[mi][j][2*hh+1]*acc2[mi][j][2*hh+1];
                if (j < 4) s0 += p; else s1 += p;
            }
            s0 += __shfl_xor_sync(0xffffffffu, s0, 1);
            s0 += __shfl_xor_sync(0xffffffffu, s0, 2);
            s1 += __shfl_xor_sync(0xffffffffu, s1, 1);
            s1 += __shfl_xor_sync(0xffffffffu, s1, 2);
            if ((lane & 3) == 0) {
                g_logits[((size_t)node*NHD + 2*wc    )*KK + kk] = s0*(1.f/32.f);
                g_logits[((size_t)node*NHD + 2*wc + 1)*KK + kk] = s1*(1.f/32.f);
            }
        }
    CP_WAIT0(); __syncthreads();

    float accv[2][8][4] = {};
    gemm3(sb, lane, wr, wc, accv);                 // Vh = hKV @ Wv1
    __syncthreads();

    stage_a_cp(sb, g_hEhi, g_hElo, nullptr, base, t);
    stage_w_cp(sb, bv0, t);
    CP_COMMIT(); CP_WAIT0();
    __syncthreads();

    gemm3(sb, lane, wr, wc, accv);                 // Vh += hE @ Wv0

    #pragma unroll
    for (int mi = 0; mi < 2; ++mi)
        #pragma unroll
        for (int hh = 0; hh < 2; ++hh) {
            long row = base + 32*wr + 16*mi + 8*hh + (lane >> 2);
            #pragma unroll
            for (int j = 0; j < 8; ++j) {
                int col = 64*wc + 8*j + 2*(lane & 3);
                *(float2*)(g_Vh + (size_t)row*128 + col) =
                    make_float2(accv[mi][j][2*hh], accv[mi][j][2*hh+1]);
            }
        }
}

// ==================== k_fc1: h_E = LN(relu([hE, hKV, hVself] @ fc1 + b)) ====
__global__ __launch_bounds__(128, 2) void k_fc1(const int* __restrict__ E_idx,
                                                const float* __restrict__ fc1b,
                                                const float* __restrict__ ng,
                                                const float* __restrict__ nb) {
    extern __shared__ char smc[];
    __shared__ int grow[64], grow2[64];
    __shared__ float reds[128], reds2[128];
    uint32_t sb = smem_u32(smc);
    int t = threadIdx.x, lane = t & 31, wid = t >> 5, wr = wid & 1, wc = wid >> 1;
    long base = (long)blockIdx.x*64;

    if (t < 64) {
        long e = base + t;
        grow[t]  = (int)(e/(LL*KK))*LL + E_idx[e];
        grow2[t] = (int)(e / KK);
    }
    stage_a_cp(sb, g_hEhi, g_hElo, nullptr, base, t);
    stage_w_cp(sb, 17, t);
    CP_COMMIT(); CP_WAIT0();
    __syncthreads();

    float acc[2][8][4] = {};
    gemm3(sb, lane, wr, wc, acc);
    __syncthreads();

    stage_a_cp(sb, g_hVhi, g_hVlo, grow, 0, t);
    stage_w_cp(sb, 18, t);
    CP_COMMIT(); CP_WAIT0();
    __syncthreads();

    gemm3(sb, lane, wr, wc, acc);
    __syncthreads();

    stage_a_cp(sb, g_hVhi, g_hVlo, grow2, 0, t);
    stage_w_cp(sb, 19, t);
    CP_COMMIT(); CP_WAIT0();
    __syncthreads();

    gemm3(sb, lane, wr, wc, acc);

    #pragma unroll
    for (int mi = 0; mi < 2; ++mi)
        #pragma unroll
        for (int hh = 0; hh < 2; ++hh) {
            int r = 32*wr + 16*mi + 8*hh + (lane >> 2);
            float s = 0.f, s2 = 0.f;
            #pragma unroll
            for (int j = 0; j < 8; ++j) {
                int col = 64*wc + 8*j + 2*(lane & 3);
                float x = fmaxf(acc[mi][j][2*hh]   + fc1b[col],     0.f);
                float y = fmaxf(acc[mi][j][2*hh+1] + fc1b[col + 1], 0.f);
                acc[mi][j][2*hh] = x; acc[mi][j][2*hh+1] = y;
                s += x + y; s2 += x*x + y*y;
            }
            s  += __shfl_xor_sync(0xffffffffu, s, 1);
            s  += __shfl_xor_sync(0xffffffffu, s, 2);
            s2 += __shfl_xor_sync(0xffffffffu, s2, 1);
            s2 += __shfl_xor_sync(0xffffffffu, s2, 2);
            if ((lane & 3) == 0) { reds[r*2 + wc] = s; reds2[r*2 + wc] = s2; }
        }
    __syncthreads();

    #pragma unroll
    for (int mi = 0; mi < 2; ++mi)
        #pragma unroll
        for (int hh = 0; hh < 2; ++hh) {
            int r = 32*wr + 16*mi + 8*hh + (lane >> 2);
            float s  = reds[r*2] + reds[r*2 + 1];
            float s2 = reds2[r*2] + reds2[r*2 + 1];
            float mu  = s*(1.f/128.f);
            float var = fmaxf((s2 - 128.f*mu*mu)*(1.f/127.f), 0.f);
            float rs  = 1.f/(sqrtf(var + EPSX) + EPSX);
            long row = base + r;
            #pragma unroll
            for (int j = 0; j < 8; ++j) {
                int col = 64*wc + 8*j + 2*(lane & 3);
                float x = ng[col    ]*(acc[mi][j][2*hh]   - mu)*rs + nb[col];
                float y = ng[col + 1]*(acc[mi][j][2*hh+1] - mu)*rs + nb[col + 1];
                uint32_t h, l; hilo2(x, y, h, l);
                *(uint32_t*)((__nv_bfloat16*)g_hEhi + (size_t)row*128 + col) = h;
                *(uint32_t*)((__nv_bfloat16*)g_hElo + (size_t)row*128 + col) = l;
            }
        }
}

// ==================== k_attn (fp32): softmax, attend*Vh, @Wo, residual+LN ====
__device__ __forceinline__ float2 ffma2(float2 d, float2 a, float2 b) {
    unsigned long long du = *reinterpret_cast<unsigned long long*>(&d);
    unsigned long long au = *reinterpret_cast<unsigned long long*>(&a);
    unsigned long long bu = *reinterpret_cast<unsigned long long*>(&b);
    asm("fma.rn.f32x2 %0, %1, %2, %0;" : "+l"(du) : "l"(au), "l"(bu));
    return *reinterpret_cast<float2*>(&du);
}
__device__ __forceinline__ void stage_mat128(float* ws, const float* __restrict__ W,
                                             int t, int nthreads) {
    for (int i = t; i < (128*128)/4; i += nthreads)
        reinterpret_cast<float4*>(ws)[i] = reinterpret_cast<const float4*>(W)[i];
}
__device__ __forceinline__ void tile_fma(const float* a_s, const float* w_s,
                                         int n0, int c0, float2 acc[4][2]) {
    #pragma unroll 8
    for (int j = 0; j < 128; ++j) {
        float2 w0 = *reinterpret_cast<const float2*>(&w_s[j*128 + c0]);
        float2 w1 = *reinterpret_cast<const float2*>(&w_s[j*128 + c0 + 2]);
        #pragma unroll
        for (int r = 0; r < 4; ++r) {
            float a = a_s[(n0 + r)*128 + j];
            float2 a2 = make_float2(a, a);
            acc[r][0] = ffma2(acc[r][0], a2, w0);
            acc[r][1] = ffma2(acc[r][1], a2, w1);
        }
    }
}

__global__ __launch_bounds__(256) void k_attn(const int* __restrict__ E_idx,
                                              const float* __restrict__ mask,
                                              const float* __restrict__ Wo,
                                              const float* __restrict__ lng,
                                              const float* __restrict__ lnb) {
    extern __shared__ float smf[];
    float* w_s = smf;
    float* a_s = smf + 128*128;
    __shared__ float att_s[32*NHD*KK];
    int t = threadIdx.x, tx = t & 31, ty = t >> 5;
    int n0 = ty*4, c0 = tx*4;
    int base = blockIdx.x*32;

    if (t < 128) {
        int nn = t >> 2, h = t & 3;
        int node = base + nn;
        int b = node / LL;
        float msel = mask[node];
        const int* eidx = &E_idx[node*KK];
        const float* lg = &g_logits[((size_t)node*NHD + h)*KK];
        float mk[KK], lv[KK];
        float mx = -3.4e38f;
        #pragma unroll
        for (int k = 0; k < KK; ++k) {
            int gi = b*LL + eidx[k];
            mk[k] = msel*mask[gi];
            lv[k] = lg[k];
            if (mk[k] > 0.f && lv[k] > mx) mx = lv[k];
        }
        float s = 0.f;
        #pragma unroll
        for (int k = 0; k < KK; ++k) {
            float e = (mk[k] > 0.f) ? __expf(lv[k] - mx) : 0.f;
            lv[k] = e; s += e;
        }
        float inv = (s > 0.f) ? (1.f/s) : 0.f;
        #pragma unroll
        for (int k = 0; k < KK; ++k)
            att_s[nn*(NHD*KK) + h*KK + k] = mk[k]*lv[k]*inv;
    }
    __syncthreads();

    #pragma unroll
    for (int r = 0; r < 4; ++r) {
        int nn = n0 + r;
        float4 u = make_float4(0.f, 0.f, 0.f, 0.f);
        const float* vh = &g_Vh[(size_t)(base + nn)*KK*128 + c0];
        const float* at = &att_s[nn*(NHD*KK) + (tx >> 3)*KK];
        #pragma unroll 6
        for (int k = 0; k < KK; ++k) {
            float a = at[k];
            float4 v = *reinterpret_cast<const float4*>(&vh[k*128]);
            u.x += a*v.x; u.y += a*v.y; u.z += a*v.z; u.w += a*v.w;
        }
        *reinterpret_cast<float4*>(&a_s[nn*128 + c0]) = u;
    }
    stage_mat128(w_s, Wo, t, 256);
    __syncthreads();

    float2 acc[4][2] = {};
    tile_fma(a_s, w_s, n0, c0, acc);

    float4 gv  = *reinterpret_cast<const float4*>(&lng[c0]);
    float4 bv2 = *reinterpret_cast<const float4*>(&lnb[c0]);
    #pragma unroll
    for (int r = 0; r < 4; ++r) {
        int node = base + n0 + r;
        float4 hv = *reinterpret_cast<const float4*>(&g_hV[node*128 + c0]);
        float x0 = hv.x + acc[r][0].x, x1 = hv.y + acc[r][0].y;
        float x2 = hv.z + acc[r][1].x, x3 = hv.w + acc[r][1].y;
        float s  = x0 + x1 + x2 + x3;
        float s2 = x0*x0 + x1*x1 + x2*x2 + x3*x3;
        #pragma unroll
        for (int o = 16; o > 0; o >>= 1) {
            s  += __shfl_xor_sync(0xffffffffu, s,  o);
            s2 += __shfl_xor_sync(0xffffffffu, s2, o);
        }
        float mu  = s*(1.f/128.f);
        float var = fmaxf((s2 - 128.f*mu*mu)*(1.f/127.f), 0.f);
        float rs  = 1.f/(sqrtf(var + EPSX) + EPSX);
        float m   = mask[node];
        float4 o4;
        o4.x = m*(gv.x*(x0 - mu)*rs + bv2.x);
        o4.y = m*(gv.y*(x1 - mu)*rs + bv2.y);
        o4.z = m*(gv.z*(x2 - mu)*rs + bv2.z);
        o4.w = m*(gv.w*(x3 - mu)*rs + bv2.w);
        *reinterpret_cast<float4*>(&g_hV[node*128 + c0]) = o4;
        uint2 h, l; hilo4(o4, h, l);
        *(uint2*)((__nv_bfloat16*)g_hVhi + (size_t)node*128 + c0) = h;
        *(uint2*)((__nv_bfloat16*)g_hVlo + (size_t)node*128 + c0) = l;
    }
}

__global__ void k_copy(float* __restrict__ out) {
    int i = blockIdx.x*blockDim.x + threadIdx.x;
    reinterpret_cast<float4*>(out)[i] = reinterpret_cast<const float4*>(g_hV)[i];
}

// =========================================================================
extern "C" void kernel_launch(void* const* d_in, const int* in_sizes, int n_in,
                              void* d_out, int out_size) {
    const float* V      = (const float*)d_in[0];
    const float* E      = (const float*)d_in[1];
    const int*   E_idx  = (const int*)  d_in[2];
    const float* mask   = (const float*)d_in[3];
    const float* Ws_w   = (const float*)d_in[4];
    const float* Ws_b   = (const float*)d_in[5];
    const float* Wt_w   = (const float*)d_in[6];
    const float* Wt_b   = (const float*)d_in[7];
    const float* Wq     = (const float*)d_in[8];
    const float* Wk1    = (const float*)d_in[9];
    const float* Wk2    = (const float*)d_in[10];
    const float* Wv     = (const float*)d_in[11];
    const float* Wo     = (const float*)d_in[12];
    const float* ln_g   = (const float*)d_in[13];
    const float* ln_b   = (const float*)d_in[14];
    const float* fc1_w  = (const float*)d_in[15];
    const float* fc1_b  = (const float*)d_in[16];
    const float* norm_g = (const float*)d_in[17];
    const float* norm_b = (const float*)d_in[18];

    const int SMA = (128*128 + 32*128)*4;
    cudaFuncSetAttribute(k_proj, cudaFuncAttributeMaxDynamicSharedMemorySize, SM_GEMM);
    cudaFuncSetAttribute(k_lv,   cudaFuncAttributeMaxDynamicSharedMemorySize, SM_GEMM);
    cudaFuncSetAttribute(k_fc1,  cudaFuncAttributeMaxDynamicSharedMemorySize, SM_GEMM);
    cudaFuncSetAttribute(k_attn, cudaFuncAttributeMaxDynamicSharedMemorySize, SMA);

    void *phV, *pQ, *pVinh, *pVinl, *pEinh, *pEinl, *phVh, *phVl, *phEh, *phEl;
    cudaGetSymbolAddress(&phV,  g_hV);
    cudaGetSymbolAddress(&pQ,   g_Q);
    cudaGetSymbolAddress(&pVinh, g_Vinhi);  cudaGetSymbolAddress(&pVinl, g_Vinlo);
    cudaGetSymbolAddress(&pEinh, g_Einhi);  cudaGetSymbolAddress(&pEinl, g_Einlo);
    cudaGetSymbolAddress(&phVh, g_hVhi);    cudaGetSymbolAddress(&phVl, g_hVlo);
    cudaGetSymbolAddress(&phEh, g_hEhi);    cudaGetSymbolAddress(&phEl, g_hElo);

    const int PGRID = 296;   // 2 CTAs/SM * 148 SMs (persistent)

    k_wconv_all<<<(23*16384 + 255)/256, 256>>>(Ws_w, Wt_w, Wq, Wk1, Wk2, Wv, fc1_w, Wo);
    k_fconv_all<<<((NNODE + NE)*32 + 255)/256, 256>>>(V, E, (uint2*)pVinh, (uint2*)pVinl,
                                                      (uint2*)pEinh, (uint2*)pEinl);
    k_proj<<<128, 128, SM_GEMM>>>((const uint4*)pVinh, (const uint4*)pVinl, 0,
                                  Ws_b, (float*)phV,
                                  (__nv_bfloat16*)phVh, (__nv_bfloat16*)phVl, NNODE/64);
    k_proj<<<PGRID, 128, SM_GEMM>>>((const uint4*)pEinh, (const uint4*)pEinl, 1,
                                    Wt_b, nullptr,
                                    (__nv_bfloat16*)phEh, (__nv_bfloat16*)phEl, NE/64);

    for (int i = 0; i < NLAY; ++i) {
        k_proj<<<128, 128, SM_GEMM>>>((const uint4*)phVh, (const uint4*)phVl,
                                      2 + i, nullptr, (float*)pQ, nullptr, nullptr, NNODE/64);
        k_lv<<<NE/64, 128, SM_GEMM>>>(E_idx, 5 + i, 8 + i, 11 + 2*i, 12 + 2*i);
        k_attn<<<NNODE/32, 256, SMA>>>(E_idx, mask, Wo + i*128*128,
                                       ln_g + i*128, ln_b + i*128);
        k_fc1<<<NE/64, 128, SM_GEMM>>>(E_idx, fc1_b, norm_g, norm_b);
    }

    k_copy<<<(NNODE*128/4)/256, 256>>>((float*)d_out);
    (void)in_sizes; (void)n_in; (void)out_size;
}

// round 14
// speedup vs baseline: 1.2267x; 1.0069x over previous
#include <cuda_runtime.h>
#include <cuda_bf16.h>
#include <stdint.h>
#include <math.h>

#define BB 4
#define LL 2048
#define KK 30
#define NHD 4
#define NLAY 3
#define NNODE (BB*LL)        /* 8192   */
#define NE (NNODE*KK)        /* 245760 */
#define EPSX 1e-6f

// ==================== device scratch (static, no allocation) ====================
__device__ float g_hV[NNODE*128];
__device__ float g_Q[NNODE*128];
__device__ float g_Vh[(size_t)NE*128];
__device__ float g_logits[(size_t)NNODE*NHD*KK];
__device__ __nv_bfloat16 g_wbhi[23*16384], g_wblo[23*16384];   // weights [n][k] bf16
__device__ uint4 g_hVhi[NNODE*16], g_hVlo[NNODE*16];
__device__ uint4 g_Vinhi[NNODE*16], g_Vinlo[NNODE*16];
__device__ uint4 g_Einhi[(size_t)NE*16], g_Einlo[(size_t)NE*16];
__device__ uint4 g_hEhi[(size_t)NE*16],  g_hElo[(size_t)NE*16];

// ==================== helpers ====================
__device__ __forceinline__ uint32_t smem_u32(const void* p) {
    uint32_t a;
    asm("{ .reg .u64 tmp; cvta.to.shared.u64 tmp, %1; cvt.u32.u64 %0, tmp; }"
        : "=r"(a) : "l"(p));
    return a;
}
__device__ __forceinline__ void ldsm4(uint32_t r[4], uint32_t addr) {
    asm volatile("ldmatrix.sync.aligned.m8n8.x4.shared.b16 {%0,%1,%2,%3}, [%4];"
        : "=r"(r[0]), "=r"(r[1]), "=r"(r[2]), "=r"(r[3]) : "r"(addr));
}
__device__ __forceinline__ void mma16816(float c[4], const uint32_t a[4], const uint32_t b[2]) {
    asm volatile("mma.sync.aligned.m16n8k16.row.col.f32.bf16.bf16.f32 "
        "{%0,%1,%2,%3}, {%4,%5,%6,%7}, {%8,%9}, {%0,%1,%2,%3};"
        : "+f"(c[0]), "+f"(c[1]), "+f"(c[2]), "+f"(c[3])
        : "r"(a[0]), "r"(a[1]), "r"(a[2]), "r"(a[3]), "r"(b[0]), "r"(b[1]));
}
__device__ __forceinline__ void hilo2(float x, float y, uint32_t& h, uint32_t& l) {
    __nv_bfloat16 hx = __float2bfloat16_rn(x), hy = __float2bfloat16_rn(y);
    __nv_bfloat16 lx = __float2bfloat16_rn(x - __bfloat162float(hx));
    __nv_bfloat16 ly = __float2bfloat16_rn(y - __bfloat162float(hy));
    h = (uint32_t)__bfloat16_as_ushort(hx) | ((uint32_t)__bfloat16_as_ushort(hy) << 16);
    l = (uint32_t)__bfloat16_as_ushort(lx) | ((uint32_t)__bfloat16_as_ushort(ly) << 16);
}
__device__ __forceinline__ void hilo4(float4 v, uint2& h, uint2& l) {
    hilo2(v.x, v.y, h.x, l.x);
    hilo2(v.z, v.w, h.y, l.y);
}
__device__ __forceinline__ void cpa16(uint32_t dst, const void* src) {
    asm volatile("cp.async.cg.shared.global [%0], [%1], 16;" :: "r"(dst), "l"(src) : "memory");
}
#define CP_COMMIT() asm volatile("cp.async.commit_group;" ::: "memory")
#define CP_WAIT0()  asm volatile("cp.async.wait_group 0;" ::: "memory")

// ==================== smem layout ====================
#define A1B 17408                 /* 64*272                 */
#define W1B 34816                 /* 128*272                */
#define OFF_A  0                  /* A hi @0, A lo @A1B     */
#define OFF_W  (2*A1B)            /* W hi @OFF_W, lo +W1B   */
#define SM_GEMM (2*A1B + 2*W1B)   /* 104448 -> 2 CTAs/SM    */

// 128-thread stagers
__device__ __forceinline__ void stage_a_cp(uint32_t sb, const uint4* ghi,
                                           const uint4* glo, const int* grow,
                                           long base, int t) {
    #pragma unroll
    for (int i = 0; i < 8; ++i) {
        int idx = t + 128*i;              // 1024 chunks = 64 rows * 16
        int row = idx >> 4, c = idx & 15;
        long gr = grow ? (long)grow[row] : (base + row);
        uint32_t d = (uint32_t)(row*272 + c*16);
        cpa16(sb + OFF_A + d,       ghi + gr*16 + c);
        cpa16(sb + OFF_A + A1B + d, glo + gr*16 + c);
    }
}
__device__ __forceinline__ void stage_w_cp(uint32_t sb, int block, int t) {
    const uint4* sh = (const uint4*)(g_wbhi + (size_t)block*16384);
    const uint4* sl = (const uint4*)(g_wblo + (size_t)block*16384);
    #pragma unroll
    for (int i = 0; i < 16; ++i) {
        int idx = t + 128*i;              // 2048 chunks = 128 rows * 16
        int row = idx >> 4, c = idx & 15;
        uint32_t d = (uint32_t)(row*272 + c*16);
        cpa16(sb + OFF_W + d,       sh + idx);
        cpa16(sb + OFF_W + W1B + d, sl + idx);
    }
}

// 3-term split GEMM on 64x128 tile; 4 warps, warp tile 32x64.
// TERM-MAJOR MMA ordering: consecutive writes to the same accumulator are
// separated by 16 independent MMAs (breaks the HMMA RAW chain).
__device__ __forceinline__ void gemm3(uint32_t sb, int lane, int wr, int wc,
                                      float acc[2][8][4]) {
    uint32_t arow = (uint32_t)(32*wr + (lane & 15));
    uint32_t acol = (uint32_t)((lane >> 4) << 3);
    uint32_t brow = (uint32_t)(64*wc + (lane & 7) + ((lane >> 4) << 3));
    uint32_t bcol = (uint32_t)(((lane >> 3) & 1) << 3);
    #pragma unroll 2
    for (int ks = 0; ks < 8; ++ks) {
        uint32_t k0 = (uint32_t)(ks*16);
        uint32_t ah[2][4], al[2][4];
        #pragma unroll
        for (int mi = 0; mi < 2; ++mi) {
            uint32_t off = ((arow + 16u*mi)*136u + k0 + acol)*2u;
            ldsm4(ah[mi], sb + OFF_A + off);
            ldsm4(al[mi], sb + OFF_A + A1B + off);
        }
        uint32_t bh[8][2], bl[8][2];
        #pragma unroll
        for (int jp = 0; jp < 4; ++jp) {
            uint32_t off = ((brow + 16u*jp)*136u + k0 + bcol)*2u;
            uint32_t r[4];
            ldsm4(r, sb + OFF_W + off);
            bh[2*jp][0] = r[0]; bh[2*jp][1] = r[1];
            bh[2*jp+1][0] = r[2]; bh[2*jp+1][1] = r[3];
            ldsm4(r, sb + OFF_W + W1B + off);
            bl[2*jp][0] = r[0]; bl[2*jp][1] = r[1];
            bl[2*jp+1][0] = r[2]; bl[2*jp+1][1] = r[3];
        }
        // term 1: Ah * Wh  (16 independent MMAs)
        #pragma unroll
        for (int mi = 0; mi < 2; ++mi)
            #pragma unroll
            for (int j = 0; j < 8; ++j)
                mma16816(acc[mi][j], ah[mi], bh[j]);
        // term 2: Ah * Wl
        #pragma unroll
        for (int mi = 0; mi < 2; ++mi)
            #pragma unroll
            for (int j = 0; j < 8; ++j)
                mma16816(acc[mi][j], ah[mi], bl[j]);
        // term 3: Al * Wh
        #pragma unroll
        for (int mi = 0; mi < 2; ++mi)
            #pragma unroll
            for (int j = 0; j < 8; ++j)
                mma16816(acc[mi][j], al[mi], bh[j]);
    }
}

// ==================== conversion kernels ====================
// blocks: 0 Ws, 1 Wt, 2-4 Wq, 5-7 Wk1, 8-10 Wk2, 11-16 Wv, 17-19 fc1, 20-22 Wo
__global__ void k_wconv_all(const float* __restrict__ Ws, const float* __restrict__ Wt,
                            const float* __restrict__ Wq, const float* __restrict__ Wk1,
                            const float* __restrict__ Wk2, const float* __restrict__ Wv,
                            const float* __restrict__ fc1, const float* __restrict__ Wo) {
    int i = blockIdx.x*blockDim.x + threadIdx.x;
    if (i >= 23*16384) return;
    int blk = i >> 14, r = i & 16383, n = r >> 7, k = r & 127;
    const float* src; int sub;
    if (blk == 0)       { src = Ws;  sub = 0; }
    else if (blk == 1)  { src = Wt;  sub = 0; }
    else if (blk < 5)   { src = Wq;  sub = blk - 2; }
    else if (blk < 8)   { src = Wk1; sub = blk - 5; }
    else if (blk < 11)  { src = Wk2; sub = blk - 8; }
    else if (blk < 17)  { src = Wv;  sub = blk - 11; }
    else if (blk < 20)  { src = fc1; sub = blk - 17; }
    else                { src = Wo;  sub = blk - 20; }
    float v = src[(size_t)sub*16384 + k*128 + n];
    __nv_bfloat16 h = __float2bfloat16_rn(v);
    __nv_bfloat16 l = __float2bfloat16_rn(v - __bfloat162float(h));
    size_t e = (size_t)blk*16384 + n*128 + k;
    g_wbhi[e] = h; g_wblo[e] = l;
}

__global__ void k_fconv_all(const float* __restrict__ V, const float* __restrict__ E,
                            uint2* __restrict__ vhi, uint2* __restrict__ vlo,
                            uint2* __restrict__ ehi, uint2* __restrict__ elo) {
    int i = blockIdx.x*blockDim.x + threadIdx.x;
    int nv = NNODE*32;
    if (i < nv) {
        float4 v = ((const float4*)V)[i];
        uint2 h, l; hilo4(v, h, l);
        vhi[i] = h; vlo[i] = l;
    } else {
        long j = (long)i - nv;
        if (j >= (long)NE*32) return;
        float4 v = ((const float4*)E)[j];
        uint2 h, l; hilo4(v, h, l);
        ehi[j] = h; elo[j] = l;
    }
}

// ==================== k_proj: PERSISTENT. out = A @ W^T (+bias) ====
__global__ __launch_bounds__(128, 2) void k_proj(const uint4* __restrict__ ahi,
                                                 const uint4* __restrict__ alo,
                                                 int wblock,
                                                 const float* __restrict__ bias,
                                                 float* __restrict__ outf,
                                                 __nv_bfloat16* __restrict__ outhi,
                                                 __nv_bfloat16* __restrict__ outlo,
                                                 int ntiles) {
    extern __shared__ char smc[];
    uint32_t sb = smem_u32(smc);
    int t = threadIdx.x, lane = t & 31, wid = t >> 5, wr = wid & 1, wc = wid >> 1;

    stage_w_cp(sb, wblock, t);
    int tile = blockIdx.x;
    if (tile < ntiles)
        stage_a_cp(sb, ahi, alo, nullptr, (long)tile*64, t);
    CP_COMMIT(); CP_WAIT0();
    __syncthreads();

    for (; tile < ntiles; tile += gridDim.x) {
        float acc[2][8][4] = {};
        gemm3(sb, lane, wr, wc, acc);
        __syncthreads();                      // all warps done reading A

        int nxt = tile + gridDim.x;
        if (nxt < ntiles) {
            stage_a_cp(sb, ahi, alo, nullptr, (long)nxt*64, t);
            CP_COMMIT();
        }

        long base = (long)tile*64;
        #pragma unroll
        for (int mi = 0; mi < 2; ++mi)
            #pragma unroll
            for (int hh = 0; hh < 2; ++hh) {
                long row = base + 32*wr + 16*mi + 8*hh + (lane >> 2);
                #pragma unroll
                for (int j = 0; j < 8; ++j) {
                    int col = 64*wc + 8*j + 2*(lane & 3);
                    float x = acc[mi][j][2*hh], y = acc[mi][j][2*hh + 1];
                    if (bias) { x += bias[col]; y += bias[col + 1]; }
                    if (outf) *(float2*)(outf + row*128 + col) = make_float2(x, y);
                    if (outhi) {
                        uint32_t h, l; hilo2(x, y, h, l);
                        *(uint32_t*)(outhi + row*128 + col) = h;
                        *(uint32_t*)(outlo + row*128 + col) = l;
                    }
                }
            }
        CP_WAIT0(); __syncthreads();
    }
}

// ==================== k_lv: K1, K2 -> logits; Vh. 64 rows/CTA ====================
__global__ __launch_bounds__(128, 2) void k_lv(const int* __restrict__ E_idx,
                                               int bk1, int bk2, int bv0, int bv1) {
    extern __shared__ char smc[];
    __shared__ int grow[64];
    uint32_t sb = smem_u32(smc);
    int t = threadIdx.x, lane = t & 31, wid = t >> 5, wr = wid & 1, wc = wid >> 1;
    long base = (long)blockIdx.x*64;

    if (t < 64) {
        long e = base + t;
        grow[t] = (int)(e/(LL*KK))*LL + E_idx[e];
    }
    stage_a_cp(sb, g_hEhi, g_hElo, nullptr, base, t);
    stage_w_cp(sb, bk1, t);
    CP_COMMIT(); CP_WAIT0();
    __syncthreads();                               // grow visible too

    float acc1[2][8][4] = {};
    gemm3(sb, lane, wr, wc, acc1);                 // K1 = hE @ Wk1
    __syncthreads();

    stage_a_cp(sb, g_hVhi, g_hVlo, grow, 0, t);    // A <- gathered hV
    stage_w_cp(sb, bk2, t);
    CP_COMMIT(); CP_WAIT0();
    __syncthreads();

    float acc2[2][8][4] = {};
    gemm3(sb, lane, wr, wc, acc2);                 // K2 = hKV @ Wk2
    __syncthreads();

    // overlap: start Wv1 load, then do logits epilogue, then wait
    stage_w_cp(sb, bv1, t);
    CP_COMMIT();

    #pragma unroll
    for (int mi = 0; mi < 2; ++mi)
        #pragma unroll
        for (int hh = 0; hh < 2; ++hh) {
            int r = 32*wr + 16*mi + 8*hh + (lane >> 2);
            long e = base + r;
            int node = (int)(e / KK), kk = (int)(e - (long)node*KK);
            const float* qrow = g_Q + (size_t)node*128;
            float s0 = 0.f, s1 = 0.f;
            #pragma unroll
            for (int j = 0; j < 8; ++j) {
                int col = 64*wc + 8*j + 2*(lane & 3);
                float2 q = *(const float2*)(qrow + col);
                float p = q.x*acc1[mi][j][2*hh]  *acc2[mi][j][2*hh]
                        + q.y*acc1[mi][j][2*hh+1]*acc2[mi][j][2*hh+1];
                if (j < 4) s0 += p; else s1 += p;
            }
            s0 += __shfl_xor_sync(0xffffffffu, s0, 1);
            s0 += __shfl_xor_sync(0xffffffffu, s0, 2);
            s1 += __shfl_xor_sync(0xffffffffu, s1, 1);
            s1 += __shfl_xor_sync(0xffffffffu, s1, 2);
            if ((lane & 3) == 0) {
                g_logits[((size_t)node*NHD + 2*wc    )*KK + kk] = s0*(1.f/32.f);
                g_logits[((size_t)node*NHD + 2*wc + 1)*KK + kk] = s1*(1.f/32.f);
            }
        }
    CP_WAIT0(); __syncthreads();

    float accv[2][8][4] = {};
    gemm3(sb, lane, wr, wc, accv);                 // Vh = hKV @ Wv1
    __syncthreads();

    stage_a_cp(sb, g_hEhi, g_hElo, nullptr, base, t);
    stage_w_cp(sb, bv0, t);
    CP_COMMIT(); CP_WAIT0();
    __syncthreads();

    gemm3(sb, lane, wr, wc, accv);                 // Vh += hE @ Wv0

    #pragma unroll
    for (int mi = 0; mi < 2; ++mi)
        #pragma unroll
        for (int hh = 0; hh < 2; ++hh) {
            long row = base + 32*wr + 16*mi + 8*hh + (lane >> 2);
            #pragma unroll
            for (int j = 0; j < 8; ++j) {
                int col = 64*wc + 8*j + 2*(lane & 3);
                *(float2*)(g_Vh + (size_t)row*128 + col) =
                    make_float2(accv[mi][j][2*hh], accv[mi][j][2*hh+1]);
            }
        }
}

// ==================== k_fc1: h_E = LN(relu([hE, hKV, hVself] @ fc1 + b)) ====
__global__ __launch_bounds__(128, 2) void k_fc1(const int* __restrict__ E_idx,
                                                const float* __restrict__ fc1b,
                                                const float* __restrict__ ng,
                                                const float* __restrict__ nb) {
    extern __shared__ char smc[];
    __shared__ int grow[64], grow2[64];
    __shared__ float reds[128], reds2[128];
    uint32_t sb = smem_u32(smc);
    int t = threadIdx.x, lane = t & 31, wid = t >> 5, wr = wid & 1, wc = wid >> 1;
    long base = (long)blockIdx.x*64;

    if (t < 64) {
        long e = base + t;
        grow[t]  = (int)(e/(LL*KK))*LL + E_idx[e];
        grow2[t] = (int)(e / KK);
    }
    stage_a_cp(sb, g_hEhi, g_hElo, nullptr, base, t);
    stage_w_cp(sb, 17, t);
    CP_COMMIT(); CP_WAIT0();
    __syncthreads();

    float acc[2][8][4] = {};
    gemm3(sb, lane, wr, wc, acc);
    __syncthreads();

    stage_a_cp(sb, g_hVhi, g_hVlo, grow, 0, t);
    stage_w_cp(sb, 18, t);
    CP_COMMIT(); CP_WAIT0();
    __syncthreads();

    gemm3(sb, lane, wr, wc, acc);
    __syncthreads();

    stage_a_cp(sb, g_hVhi, g_hVlo, grow2, 0, t);
    stage_w_cp(sb, 19, t);
    CP_COMMIT(); CP_WAIT0();
    __syncthreads();

    gemm3(sb, lane, wr, wc, acc);

    #pragma unroll
    for (int mi = 0; mi < 2; ++mi)
        #pragma unroll
        for (int hh = 0; hh < 2; ++hh) {
            int r = 32*wr + 16*mi + 8*hh + (lane >> 2);
            float s = 0.f, s2 = 0.f;
            #pragma unroll
            for (int j = 0; j < 8; ++j) {
                int col = 64*wc + 8*j + 2*(lane & 3);
                float x = fmaxf(acc[mi][j][2*hh]   + fc1b[col],     0.f);
                float y = fmaxf(acc[mi][j][2*hh+1] + fc1b[col + 1], 0.f);
                acc[mi][j][2*hh] = x; acc[mi][j][2*hh+1] = y;
                s += x + y; s2 += x*x + y*y;
            }
            s  += __shfl_xor_sync(0xffffffffu, s, 1);
            s  += __shfl_xor_sync(0xffffffffu, s, 2);
            s2 += __shfl_xor_sync(0xffffffffu, s2, 1);
            s2 += __shfl_xor_sync(0xffffffffu, s2, 2);
            if ((lane & 3) == 0) { reds[r*2 + wc] = s; reds2[r*2 + wc] = s2; }
        }
    __syncthreads();

    #pragma unroll
    for (int mi = 0; mi < 2; ++mi)
        #pragma unroll
        for (int hh = 0; hh < 2; ++hh) {
            int r = 32*wr + 16*mi + 8*hh + (lane >> 2);
            float s  = reds[r*2] + reds[r*2 + 1];
            float s2 = reds2[r*2] + reds2[r*2 + 1];
            float mu  = s*(1.f/128.f);
            float var = fmaxf((s2 - 128.f*mu*mu)*(1.f/127.f), 0.f);
            float rs  = 1.f/(sqrtf(var + EPSX) + EPSX);
            long row = base + r;
            #pragma unroll
            for (int j = 0; j < 8; ++j) {
                int col = 64*wc + 8*j + 2*(lane & 3);
                float x = ng[col    ]*(acc[mi][j][2*hh]   - mu)*rs + nb[col];
                float y = ng[col + 1]*(acc[mi][j][2*hh+1] - mu)*rs + nb[col + 1];
                uint32_t h, l; hilo2(x, y, h, l);
                *(uint32_t*)((__nv_bfloat16*)g_hEhi + (size_t)row*128 + col) = h;
                *(uint32_t*)((__nv_bfloat16*)g_hElo + (size_t)row*128 + col) = l;
            }
        }
}

// ==================== k_attn (fp32): softmax, attend*Vh, @Wo, residual+LN ====
__device__ __forceinline__ float2 ffma2(float2 d, float2 a, float2 b) {
    unsigned long long du = *reinterpret_cast<unsigned long long*>(&d);
    unsigned long long au = *reinterpret_cast<unsigned long long*>(&a);
    unsigned long long bu = *reinterpret_cast<unsigned long long*>(&b);
    asm("fma.rn.f32x2 %0, %1, %2, %0;" : "+l"(du) : "l"(au), "l"(bu));
    return *reinterpret_cast<float2*>(&du);
}
__device__ __forceinline__ void stage_mat128(float* ws, const float* __restrict__ W,
                                             int t, int nthreads) {
    for (int i = t; i < (128*128)/4; i += nthreads)
        reinterpret_cast<float4*>(ws)[i] = reinterpret_cast<const float4*>(W)[i];
}
__device__ __forceinline__ void tile_fma(const float* a_s, const float* w_s,
                                         int n0, int c0, float2 acc[4][2]) {
    #pragma unroll 8
    for (int j = 0; j < 128; ++j) {
        float2 w0 = *reinterpret_cast<const float2*>(&w_s[j*128 + c0]);
        float2 w1 = *reinterpret_cast<const float2*>(&w_s[j*128 + c0 + 2]);
        #pragma unroll
        for (int r = 0; r < 4; ++r) {
            float a = a_s[(n0 + r)*128 + j];
            float2 a2 = make_float2(a, a);
            acc[r][0] = ffma2(acc[r][0], a2, w0);
            acc[r][1] = ffma2(acc[r][1], a2, w1);
        }
    }
}

__global__ __launch_bounds__(256) void k_attn(const int* __restrict__ E_idx,
                                              const float* __restrict__ mask,
                                              const float* __restrict__ Wo,
                                              const float* __restrict__ lng,
                                              const float* __restrict__ lnb) {
    extern __shared__ float smf[];
    float* w_s = smf;
    float* a_s = smf + 128*128;
    __shared__ float att_s[32*NHD*KK];
    int t = threadIdx.x, tx = t & 31, ty = t >> 5;
    int n0 = ty*4, c0 = tx*4;
    int base = blockIdx.x*32;

    if (t < 128) {
        int nn = t >> 2, h = t & 3;
        int node = base + nn;
        int b = node / LL;
        float msel = mask[node];
        const int* eidx = &E_idx[node*KK];
        const float* lg = &g_logits[((size_t)node*NHD + h)*KK];
        float mk[KK], lv[KK];
        float mx = -3.4e38f;
        #pragma unroll
        for (int k = 0; k < KK; ++k) {
            int gi = b*LL + eidx[k];
            mk[k] = msel*mask[gi];
            lv[k] = lg[k];
            if (mk[k] > 0.f && lv[k] > mx) mx = lv[k];
        }
        float s = 0.f;
        #pragma unroll
        for (int k = 0; k < KK; ++k) {
            float e = (mk[k] > 0.f) ? __expf(lv[k] - mx) : 0.f;
            lv[k] = e; s += e;
        }
        float inv = (s > 0.f) ? (1.f/s) : 0.f;
        #pragma unroll
        for (int k = 0; k < KK; ++k)
            att_s[nn*(NHD*KK) + h*KK + k] = mk[k]*lv[k]*inv;
    }
    __syncthreads();

    #pragma unroll
    for (int r = 0; r < 4; ++r) {
        int nn = n0 + r;
        float4 u = make_float4(0.f, 0.f, 0.f, 0.f);
        const float* vh = &g_Vh[(size_t)(base + nn)*KK*128 + c0];
        const float* at = &att_s[nn*(NHD*KK) + (tx >> 3)*KK];
        #pragma unroll 6
        for (int k = 0; k < KK; ++k) {
            float a = at[k];
            float4 v = *reinterpret_cast<const float4*>(&vh[k*128]);
            u.x += a*v.x; u.y += a*v.y; u.z += a*v.z; u.w += a*v.w;
        }
        *reinterpret_cast<float4*>(&a_s[nn*128 + c0]) = u;
    }
    stage_mat128(w_s, Wo, t, 256);
    __syncthreads();

    float2 acc[4][2] = {};
    tile_fma(a_s, w_s, n0, c0, acc);

    float4 gv  = *reinterpret_cast<const float4*>(&lng[c0]);
    float4 bv2 = *reinterpret_cast<const float4*>(&lnb[c0]);
    #pragma unroll
    for (int r = 0; r < 4; ++r) {
        int node = base + n0 + r;
        float4 hv = *reinterpret_cast<const float4*>(&g_hV[node*128 + c0]);
        float x0 = hv.x + acc[r][0].x, x1 = hv.y + acc[r][0].y;
        float x2 = hv.z + acc[r][1].x, x3 = hv.w + acc[r][1].y;
        float s  = x0 + x1 + x2 + x3;
        float s2 = x0*x0 + x1*x1 + x2*x2 + x3*x3;
        #pragma unroll
        for (int o = 16; o > 0; o >>= 1) {
            s  += __shfl_xor_sync(0xffffffffu, s,  o);
            s2 += __shfl_xor_sync(0xffffffffu, s2, o);
        }
        float mu  = s*(1.f/128.f);
        float var = fmaxf((s2 - 128.f*mu*mu)*(1.f/127.f), 0.f);
        float rs  = 1.f/(sqrtf(var + EPSX) + EPSX);
        float m   = mask[node];
        float4 o4;
        o4.x = m*(gv.x*(x0 - mu)*rs + bv2.x);
        o4.y = m*(gv.y*(x1 - mu)*rs + bv2.y);
        o4.z = m*(gv.z*(x2 - mu)*rs + bv2.z);
        o4.w = m*(gv.w*(x3 - mu)*rs + bv2.w);
        *reinterpret_cast<float4*>(&g_hV[node*128 + c0]) = o4;
        uint2 h, l; hilo4(o4, h, l);
        *(uint2*)((__nv_bfloat16*)g_hVhi + (size_t)node*128 + c0) = h;
        *(uint2*)((__nv_bfloat16*)g_hVlo + (size_t)node*128 + c0) = l;
    }
}

__global__ void k_copy(float* __restrict__ out) {
    int i = blockIdx.x*blockDim.x + threadIdx.x;
    reinterpret_cast<float4*>(out)[i] = reinterpret_cast<const float4*>(g_hV)[i];
}

// =========================================================================
extern "C" void kernel_launch(void* const* d_in, const int* in_sizes, int n_in,
                              void* d_out, int out_size) {
    const float* V      = (const float*)d_in[0];
    const float* E      = (const float*)d_in[1];
    const int*   E_idx  = (const int*)  d_in[2];
    const float* mask   = (const float*)d_in[3];
    const float* Ws_w   = (const float*)d_in[4];
    const float* Ws_b   = (const float*)d_in[5];
    const float* Wt_w   = (const float*)d_in[6];
    const float* Wt_b   = (const float*)d_in[7];
    const float* Wq     = (const float*)d_in[8];
    const float* Wk1    = (const float*)d_in[9];
    const float* Wk2    = (const float*)d_in[10];
    const float* Wv     = (const float*)d_in[11];
    const float* Wo     = (const float*)d_in[12];
    const float* ln_g   = (const float*)d_in[13];
    const float* ln_b   = (const float*)d_in[14];
    const float* fc1_w  = (const float*)d_in[15];
    const float* fc1_b  = (const float*)d_in[16];
    const float* norm_g = (const float*)d_in[17];
    const float* norm_b = (const float*)d_in[18];

    const int SMA = (128*128 + 32*128)*4;
    cudaFuncSetAttribute(k_proj, cudaFuncAttributeMaxDynamicSharedMemorySize, SM_GEMM);
    cudaFuncSetAttribute(k_lv,   cudaFuncAttributeMaxDynamicSharedMemorySize, SM_GEMM);
    cudaFuncSetAttribute(k_fc1,  cudaFuncAttributeMaxDynamicSharedMemorySize, SM_GEMM);
    cudaFuncSetAttribute(k_attn, cudaFuncAttributeMaxDynamicSharedMemorySize, SMA);

    void *phV, *pQ, *pVinh, *pVinl, *pEinh, *pEinl, *phVh, *phVl, *phEh, *phEl;
    cudaGetSymbolAddress(&phV,  g_hV);
    cudaGetSymbolAddress(&pQ,   g_Q);
    cudaGetSymbolAddress(&pVinh, g_Vinhi);  cudaGetSymbolAddress(&pVinl, g_Vinlo);
    cudaGetSymbolAddress(&pEinh, g_Einhi);  cudaGetSymbolAddress(&pEinl, g_Einlo);
    cudaGetSymbolAddress(&phVh, g_hVhi);    cudaGetSymbolAddress(&phVl, g_hVlo);
    cudaGetSymbolAddress(&phEh, g_hEhi);    cudaGetSymbolAddress(&phEl, g_hElo);

    const int PGRID = 296;   // 2 CTAs/SM * 148 SMs (persistent)

    k_wconv_all<<<(23*16384 + 255)/256, 256>>>(Ws_w, Wt_w, Wq, Wk1, Wk2, Wv, fc1_w, Wo);
    k_fconv_all<<<((NNODE + NE)*32 + 255)/256, 256>>>(V, E, (uint2*)pVinh, (uint2*)pVinl,
                                                      (uint2*)pEinh, (uint2*)pEinl);
    k_proj<<<128, 128, SM_GEMM>>>((const uint4*)pVinh, (const uint4*)pVinl, 0,
                                  Ws_b, (float*)phV,
                                  (__nv_bfloat16*)phVh, (__nv_bfloat16*)phVl, NNODE/64);
    k_proj<<<PGRID, 128, SM_GEMM>>>((const uint4*)pEinh, (const uint4*)pEinl, 1,
                                    Wt_b, nullptr,
                                    (__nv_bfloat16*)phEh, (__nv_bfloat16*)phEl, NE/64);

    for (int i = 0; i < NLAY; ++i) {
        k_proj<<<128, 128, SM_GEMM>>>((const uint4*)phVh, (const uint4*)phVl,
                                      2 + i, nullptr, (float*)pQ, nullptr, nullptr, NNODE/64);
        k_lv<<<NE/64, 128, SM_GEMM>>>(E_idx, 5 + i, 8 + i, 11 + 2*i, 12 + 2*i);
        k_attn<<<NNODE/32, 256, SMA>>>(E_idx, mask, Wo + i*128*128,
                                       ln_g + i*128, ln_b + i*128);
        k_fc1<<<NE/64, 128, SM_GEMM>>>(E_idx, fc1_b, norm_g, norm_b);
    }

    k_copy<<<(NNODE*128/4)/256, 256>>>((float*)d_out);
    (void)in_sizes; (void)n_in; (void)out_size;
}

// round 15
// speedup vs baseline: 1.2447x; 1.0147x over previous
#include <cuda_runtime.h>
#include <cuda_bf16.h>
#include <stdint.h>
#include <math.h>

#define BB 4
#define LL 2048
#define KK 30
#define NHD 4
#define NLAY 3
#define NNODE (BB*LL)        /* 8192   */
#define NE (NNODE*KK)        /* 245760 */
#define EPSX 1e-6f

// ==================== device scratch (static, no allocation) ====================
__device__ float g_hV[NNODE*128];
__device__ float g_Q[NNODE*128];
__device__ float g_Vh[(size_t)NE*128];
__device__ float g_logits[(size_t)NNODE*NHD*KK];
__device__ __nv_bfloat16 g_wbhi[23*16384], g_wblo[23*16384];   // weights [n][k] bf16
__device__ uint4 g_hVhi[NNODE*16], g_hVlo[NNODE*16];
__device__ uint4 g_hEhi[(size_t)NE*16],  g_hElo[(size_t)NE*16];

// ==================== helpers ====================
__device__ __forceinline__ uint32_t smem_u32(const void* p) {
    uint32_t a;
    asm("{ .reg .u64 tmp; cvta.to.shared.u64 tmp, %1; cvt.u32.u64 %0, tmp; }"
        : "=r"(a) : "l"(p));
    return a;
}
__device__ __forceinline__ void ldsm4(uint32_t r[4], uint32_t addr) {
    asm volatile("ldmatrix.sync.aligned.m8n8.x4.shared.b16 {%0,%1,%2,%3}, [%4];"
        : "=r"(r[0]), "=r"(r[1]), "=r"(r[2]), "=r"(r[3]) : "r"(addr));
}
__device__ __forceinline__ void mma16816(float c[4], const uint32_t a[4], const uint32_t b[2]) {
    asm volatile("mma.sync.aligned.m16n8k16.row.col.f32.bf16.bf16.f32 "
        "{%0,%1,%2,%3}, {%4,%5,%6,%7}, {%8,%9}, {%0,%1,%2,%3};"
        : "+f"(c[0]), "+f"(c[1]), "+f"(c[2]), "+f"(c[3])
        : "r"(a[0]), "r"(a[1]), "r"(a[2]), "r"(a[3]), "r"(b[0]), "r"(b[1]));
}
__device__ __forceinline__ void hilo2(float x, float y, uint32_t& h, uint32_t& l) {
    __nv_bfloat16 hx = __float2bfloat16_rn(x), hy = __float2bfloat16_rn(y);
    __nv_bfloat16 lx = __float2bfloat16_rn(x - __bfloat162float(hx));
    __nv_bfloat16 ly = __float2bfloat16_rn(y - __bfloat162float(hy));
    h = (uint32_t)__bfloat16_as_ushort(hx) | ((uint32_t)__bfloat16_as_ushort(hy) << 16);
    l = (uint32_t)__bfloat16_as_ushort(lx) | ((uint32_t)__bfloat16_as_ushort(ly) << 16);
}
__device__ __forceinline__ void hilo4(float4 v, uint2& h, uint2& l) {
    hilo2(v.x, v.y, h.x, l.x);
    hilo2(v.z, v.w, h.y, l.y);
}
__device__ __forceinline__ void cpa16(uint32_t dst, const void* src) {
    asm volatile("cp.async.cg.shared.global [%0], [%1], 16;" :: "r"(dst), "l"(src) : "memory");
}
#define CP_COMMIT() asm volatile("cp.async.commit_group;" ::: "memory")
#define CP_WAIT0()  asm volatile("cp.async.wait_group 0;" ::: "memory")

// ==================== smem layout ====================
#define A1B 17408                 /* 64*272                 */
#define W1B 34816                 /* 128*272                */
#define OFF_A  0                  /* A hi @0, A lo @A1B     */
#define OFF_W  (2*A1B)            /* W hi @OFF_W, lo +W1B   */
#define SM_GEMM (2*A1B + 2*W1B)   /* 104448 -> 2 CTAs/SM    */

// 128-thread stagers
__device__ __forceinline__ void stage_a_cp(uint32_t sb, const uint4* ghi,
                                           const uint4* glo, const int* grow,
                                           long base, int t) {
    #pragma unroll
    for (int i = 0; i < 8; ++i) {
        int idx = t + 128*i;              // 1024 chunks = 64 rows * 16
        int row = idx >> 4, c = idx & 15;
        long gr = grow ? (long)grow[row] : (base + row);
        uint32_t d = (uint32_t)(row*272 + c*16);
        cpa16(sb + OFF_A + d,       ghi + gr*16 + c);
        cpa16(sb + OFF_A + A1B + d, glo + gr*16 + c);
    }
}
// fp32 source: LDG float4, split to bf16 hi/lo in regs, STS both halves
__device__ __forceinline__ void stage_a_f32v(char* smc, const float4* gsrc,
                                             long base, int t) {
    #pragma unroll
    for (int i = 0; i < 16; ++i) {
        int idx = t + 128*i;              // 2048 float4 chunks = 64 rows * 32
        int row = idx >> 5, c = idx & 31;
        float4 v = gsrc[(base + row)*32 + c];
        uint2 h, l; hilo4(v, h, l);
        uint32_t d = (uint32_t)(row*272 + c*8);
        *(uint2*)(smc + OFF_A + d)       = h;
        *(uint2*)(smc + OFF_A + A1B + d) = l;
    }
}
__device__ __forceinline__ void stage_w_cp(uint32_t sb, int block, int t) {
    const uint4* sh = (const uint4*)(g_wbhi + (size_t)block*16384);
    const uint4* sl = (const uint4*)(g_wblo + (size_t)block*16384);
    #pragma unroll
    for (int i = 0; i < 16; ++i) {
        int idx = t + 128*i;              // 2048 chunks = 128 rows * 16
        int row = idx >> 4, c = idx & 15;
        uint32_t d = (uint32_t)(row*272 + c*16);
        cpa16(sb + OFF_W + d,       sh + idx);
        cpa16(sb + OFF_W + W1B + d, sl + idx);
    }
}

// 3-term split GEMM on 64x128 tile; 4 warps, warp tile 32x64. Term-major order.
__device__ __forceinline__ void gemm3(uint32_t sb, int lane, int wr, int wc,
                                      float acc[2][8][4]) {
    uint32_t arow = (uint32_t)(32*wr + (lane & 15));
    uint32_t acol = (uint32_t)((lane >> 4) << 3);
    uint32_t brow = (uint32_t)(64*wc + (lane & 7) + ((lane >> 4) << 3));
    uint32_t bcol = (uint32_t)(((lane >> 3) & 1) << 3);
    #pragma unroll 2
    for (int ks = 0; ks < 8; ++ks) {
        uint32_t k0 = (uint32_t)(ks*16);
        uint32_t ah[2][4], al[2][4];
        #pragma unroll
        for (int mi = 0; mi < 2; ++mi) {
            uint32_t off = ((arow + 16u*mi)*136u + k0 + acol)*2u;
            ldsm4(ah[mi], sb + OFF_A + off);
            ldsm4(al[mi], sb + OFF_A + A1B + off);
        }
        uint32_t bh[8][2], bl[8][2];
        #pragma unroll
        for (int jp = 0; jp < 4; ++jp) {
            uint32_t off = ((brow + 16u*jp)*136u + k0 + bcol)*2u;
            uint32_t r[4];
            ldsm4(r, sb + OFF_W + off);
            bh[2*jp][0] = r[0]; bh[2*jp][1] = r[1];
            bh[2*jp+1][0] = r[2]; bh[2*jp+1][1] = r[3];
            ldsm4(r, sb + OFF_W + W1B + off);
            bl[2*jp][0] = r[0]; bl[2*jp][1] = r[1];
            bl[2*jp+1][0] = r[2]; bl[2*jp+1][1] = r[3];
        }
        #pragma unroll
        for (int mi = 0; mi < 2; ++mi)
            #pragma unroll
            for (int j = 0; j < 8; ++j)
                mma16816(acc[mi][j], ah[mi], bh[j]);
        #pragma unroll
        for (int mi = 0; mi < 2; ++mi)
            #pragma unroll
            for (int j = 0; j < 8; ++j)
                mma16816(acc[mi][j], ah[mi], bl[j]);
        #pragma unroll
        for (int mi = 0; mi < 2; ++mi)
            #pragma unroll
            for (int j = 0; j < 8; ++j)
                mma16816(acc[mi][j], al[mi], bh[j]);
    }
}

// ==================== weight conversion ====================
// blocks: 0 Ws, 1 Wt, 2-4 Wq, 5-7 Wk1, 8-10 Wk2, 11-16 Wv, 17-19 fc1, 20-22 Wo
__global__ void k_wconv_all(const float* __restrict__ Ws, const float* __restrict__ Wt,
                            const float* __restrict__ Wq, const float* __restrict__ Wk1,
                            const float* __restrict__ Wk2, const float* __restrict__ Wv,
                            const float* __restrict__ fc1, const float* __restrict__ Wo) {
    int i = blockIdx.x*blockDim.x + threadIdx.x;
    if (i >= 23*16384) return;
    int blk = i >> 14, r = i & 16383, n = r >> 7, k = r & 127;
    const float* src; int sub;
    if (blk == 0)       { src = Ws;  sub = 0; }
    else if (blk == 1)  { src = Wt;  sub = 0; }
    else if (blk < 5)   { src = Wq;  sub = blk - 2; }
    else if (blk < 8)   { src = Wk1; sub = blk - 5; }
    else if (blk < 11)  { src = Wk2; sub = blk - 8; }
    else if (blk < 17)  { src = Wv;  sub = blk - 11; }
    else if (blk < 20)  { src = fc1; sub = blk - 17; }
    else                { src = Wo;  sub = blk - 20; }
    float v = src[(size_t)sub*16384 + k*128 + n];
    __nv_bfloat16 h = __float2bfloat16_rn(v);
    __nv_bfloat16 l = __float2bfloat16_rn(v - __bfloat162float(h));
    size_t e = (size_t)blk*16384 + n*128 + k;
    g_wbhi[e] = h; g_wblo[e] = l;
}

// ==================== k_projf: PERSISTENT, fp32 input, fused convert ====
__global__ __launch_bounds__(128, 2) void k_projf(const float* __restrict__ act,
                                                  int wblock,
                                                  const float* __restrict__ bias,
                                                  float* __restrict__ outf,
                                                  __nv_bfloat16* __restrict__ outhi,
                                                  __nv_bfloat16* __restrict__ outlo,
                                                  int ntiles) {
    extern __shared__ char smc[];
    uint32_t sb = smem_u32(smc);
    int t = threadIdx.x, lane = t & 31, wid = t >> 5, wr = wid & 1, wc = wid >> 1;
    const float4* gsrc = (const float4*)act;

    stage_w_cp(sb, wblock, t);
    CP_COMMIT();
    int tile = blockIdx.x;
    if (tile < ntiles)
        stage_a_f32v(smc, gsrc, (long)tile*64, t);
    CP_WAIT0();
    __syncthreads();

    for (; tile < ntiles; tile += gridDim.x) {
        float acc[2][8][4] = {};
        gemm3(sb, lane, wr, wc, acc);
        __syncthreads();

        int nxt = tile + gridDim.x;
        if (nxt < ntiles)
            stage_a_f32v(smc, gsrc, (long)nxt*64, t);   // LDG+convert+STS for next tile

        long base = (long)tile*64;
        #pragma unroll
        for (int mi = 0; mi < 2; ++mi)
            #pragma unroll
            for (int hh = 0; hh < 2; ++hh) {
                long row = base + 32*wr + 16*mi + 8*hh + (lane >> 2);
                #pragma unroll
                for (int j = 0; j < 8; ++j) {
                    int col = 64*wc + 8*j + 2*(lane & 3);
                    float x = acc[mi][j][2*hh], y = acc[mi][j][2*hh + 1];
                    if (bias) { x += bias[col]; y += bias[col + 1]; }
                    if (outf) *(float2*)(outf + row*128 + col) = make_float2(x, y);
                    if (outhi) {
                        uint32_t h, l; hilo2(x, y, h, l);
                        *(uint32_t*)(outhi + row*128 + col) = h;
                        *(uint32_t*)(outlo + row*128 + col) = l;
                    }
                }
            }
        __syncthreads();
    }
}

// ==================== k_proj: PERSISTENT, bf16-pair input ====
__global__ __launch_bounds__(128, 2) void k_proj(const uint4* __restrict__ ahi,
                                                 const uint4* __restrict__ alo,
                                                 int wblock,
                                                 const float* __restrict__ bias,
                                                 float* __restrict__ outf,
                                                 __nv_bfloat16* __restrict__ outhi,
                                                 __nv_bfloat16* __restrict__ outlo,
                                                 int ntiles) {
    extern __shared__ char smc[];
    uint32_t sb = smem_u32(smc);
    int t = threadIdx.x, lane = t & 31, wid = t >> 5, wr = wid & 1, wc = wid >> 1;

    stage_w_cp(sb, wblock, t);
    int tile = blockIdx.x;
    if (tile < ntiles)
        stage_a_cp(sb, ahi, alo, nullptr, (long)tile*64, t);
    CP_COMMIT(); CP_WAIT0();
    __syncthreads();

    for (; tile < ntiles; tile += gridDim.x) {
        float acc[2][8][4] = {};
        gemm3(sb, lane, wr, wc, acc);
        __syncthreads();

        int nxt = tile + gridDim.x;
        if (nxt < ntiles) {
            stage_a_cp(sb, ahi, alo, nullptr, (long)nxt*64, t);
            CP_COMMIT();
        }

        long base = (long)tile*64;
        #pragma unroll
        for (int mi = 0; mi < 2; ++mi)
            #pragma unroll
            for (int hh = 0; hh < 2; ++hh) {
                long row = base + 32*wr + 16*mi + 8*hh + (lane >> 2);
                #pragma unroll
                for (int j = 0; j < 8; ++j) {
                    int col = 64*wc + 8*j + 2*(lane & 3);
                    float x = acc[mi][j][2*hh], y = acc[mi][j][2*hh + 1];
                    if (bias) { x += bias[col]; y += bias[col + 1]; }
                    if (outf) *(float2*)(outf + row*128 + col) = make_float2(x, y);
                    if (outhi) {
                        uint32_t h, l; hilo2(x, y, h, l);
                        *(uint32_t*)(outhi + row*128 + col) = h;
                        *(uint32_t*)(outlo + row*128 + col) = l;
                    }
                }
            }
        CP_WAIT0(); __syncthreads();
    }
}

// ==================== k_lv: K1, K2 -> logits; Vh. 64 rows/CTA ====================
__global__ __launch_bounds__(128, 2) void k_lv(const int* __restrict__ E_idx,
                                               int bk1, int bk2, int bv0, int bv1) {
    extern __shared__ char smc[];
    __shared__ int grow[64];
    uint32_t sb = smem_u32(smc);
    int t = threadIdx.x, lane = t & 31, wid = t >> 5, wr = wid & 1, wc = wid >> 1;
    long base = (long)blockIdx.x*64;

    if (t < 64) {
        long e = base + t;
        grow[t] = (int)(e/(LL*KK))*LL + E_idx[e];
    }
    stage_a_cp(sb, g_hEhi, g_hElo, nullptr, base, t);
    stage_w_cp(sb, bk1, t);
    CP_COMMIT(); CP_WAIT0();
    __syncthreads();

    float acc1[2][8][4] = {};
    gemm3(sb, lane, wr, wc, acc1);                 // K1 = hE @ Wk1
    __syncthreads();

    stage_a_cp(sb, g_hVhi, g_hVlo, grow, 0, t);    // A <- gathered hV
    stage_w_cp(sb, bk2, t);
    CP_COMMIT(); CP_WAIT0();
    __syncthreads();

    float acc2[2][8][4] = {};
    gemm3(sb, lane, wr, wc, acc2);                 // K2 = hKV @ Wk2
    __syncthreads();

    stage_w_cp(sb, bv1, t);
    CP_COMMIT();

    #pragma unroll
    for (int mi = 0; mi < 2; ++mi)
        #pragma unroll
        for (int hh = 0; hh < 2; ++hh) {
            int r = 32*wr + 16*mi + 8*hh + (lane >> 2);
            long e = base + r;
            int node = (int)(e / KK), kk = (int)(e - (long)node*KK);
            const float* qrow = g_Q + (size_t)node*128;
            float s0 = 0.f, s1 = 0.f;
            #pragma unroll
            for (int j = 0; j < 8; ++j) {
                int col = 64*wc + 8*j + 2*(lane & 3);
                float2 q = *(const float2*)(qrow + col);
                float p = q.x*acc1[mi][j][2*hh]  *acc2[mi][j][2*hh]
                        + q.y*acc1[mi][j][2*hh+1]*acc2[mi][j][2*hh+1];
                if (j < 4) s0 += p; else s1 += p;
            }
            s0 += __shfl_xor_sync(0xffffffffu, s0, 1);
            s0 += __shfl_xor_sync(0xffffffffu, s0, 2);
            s1 += __shfl_xor_sync(0xffffffffu, s1, 1);
            s1 += __shfl_xor_sync(0xffffffffu, s1, 2);
            if ((lane & 3) == 0) {
                g_logits[((size_t)node*NHD + 2*wc    )*KK + kk] = s0*(1.f/32.f);
                g_logits[((size_t)node*NHD + 2*wc + 1)*KK + kk] = s1*(1.f/32.f);
            }
        }
    CP_WAIT0(); __syncthreads();

    float accv[2][8][4] = {};
    gemm3(sb, lane, wr, wc, accv);                 // Vh = hKV @ Wv1
    __syncthreads();

    stage_a_cp(sb, g_hEhi, g_hElo, nullptr, base, t);
    stage_w_cp(sb, bv0, t);
    CP_COMMIT(); CP_WAIT0();
    __syncthreads();

    gemm3(sb, lane, wr, wc, accv);                 // Vh += hE @ Wv0

    #pragma unroll
    for (int mi = 0; mi < 2; ++mi)
        #pragma unroll
        for (int hh = 0; hh < 2; ++hh) {
            long row = base + 32*wr + 16*mi + 8*hh + (lane >> 2);
            #pragma unroll
            for (int j = 0; j < 8; ++j) {
                int col = 64*wc + 8*j + 2*(lane & 3);
                *(float2*)(g_Vh + (size_t)row*128 + col) =
                    make_float2(accv[mi][j][2*hh], accv[mi][j][2*hh+1]);
            }
        }
}

// ==================== k_fc1: h_E = LN(relu([hE, hKV, hVself] @ fc1 + b)) ====
__global__ __launch_bounds__(128, 2) void k_fc1(const int* __restrict__ E_idx,
                                                const float* __restrict__ fc1b,
                                                const float* __restrict__ ng,
                                                const float* __restrict__ nb) {
    extern __shared__ char smc[];
    __shared__ int grow[64], grow2[64];
    __shared__ float reds[128], reds2[128];
    uint32_t sb = smem_u32(smc);
    int t = threadIdx.x, lane = t & 31, wid = t >> 5, wr = wid & 1, wc = wid >> 1;
    long base = (long)blockIdx.x*64;

    if (t < 64) {
        long e = base + t;
        grow[t]  = (int)(e/(LL*KK))*LL + E_idx[e];
        grow2[t] = (int)(e / KK);
    }
    stage_a_cp(sb, g_hEhi, g_hElo, nullptr, base, t);
    stage_w_cp(sb, 17, t);
    CP_COMMIT(); CP_WAIT0();
    __syncthreads();

    float acc[2][8][4] = {};
    gemm3(sb, lane, wr, wc, acc);
    __syncthreads();

    stage_a_cp(sb, g_hVhi, g_hVlo, grow, 0, t);
    stage_w_cp(sb, 18, t);
    CP_COMMIT(); CP_WAIT0();
    __syncthreads();

    gemm3(sb, lane, wr, wc, acc);
    __syncthreads();

    stage_a_cp(sb, g_hVhi, g_hVlo, grow2, 0, t);
    stage_w_cp(sb, 19, t);
    CP_COMMIT(); CP_WAIT0();
    __syncthreads();

    gemm3(sb, lane, wr, wc, acc);

    #pragma unroll
    for (int mi = 0; mi < 2; ++mi)
        #pragma unroll
        for (int hh = 0; hh < 2; ++hh) {
            int r = 32*wr + 16*mi + 8*hh + (lane >> 2);
            float s = 0.f, s2 = 0.f;
            #pragma unroll
            for (int j = 0; j < 8; ++j) {
                int col = 64*wc + 8*j + 2*(lane & 3);
                float x = fmaxf(acc[mi][j][2*hh]   + fc1b[col],     0.f);
                float y = fmaxf(acc[mi][j][2*hh+1] + fc1b[col + 1], 0.f);
                acc[mi][j][2*hh] = x; acc[mi][j][2*hh+1] = y;
                s += x + y; s2 += x*x + y*y;
            }
            s  += __shfl_xor_sync(0xffffffffu, s, 1);
            s  += __shfl_xor_sync(0xffffffffu, s, 2);
            s2 += __shfl_xor_sync(0xffffffffu, s2, 1);
            s2 += __shfl_xor_sync(0xffffffffu, s2, 2);
            if ((lane & 3) == 0) { reds[r*2 + wc] = s; reds2[r*2 + wc] = s2; }
        }
    __syncthreads();

    #pragma unroll
    for (int mi = 0; mi < 2; ++mi)
        #pragma unroll
        for (int hh = 0; hh < 2; ++hh) {
            int r = 32*wr + 16*mi + 8*hh + (lane >> 2);
            float s  = reds[r*2] + reds[r*2 + 1];
            float s2 = reds2[r*2] + reds2[r*2 + 1];
            float mu  = s*(1.f/128.f);
            float var = fmaxf((s2 - 128.f*mu*mu)*(1.f/127.f), 0.f);
            float rs  = 1.f/(sqrtf(var + EPSX) + EPSX);
            long row = base + r;
            #pragma unroll
            for (int j = 0; j < 8; ++j) {
                int col = 64*wc + 8*j + 2*(lane & 3);
                float x = ng[col    ]*(acc[mi][j][2*hh]   - mu)*rs + nb[col];
                float y = ng[col + 1]*(acc[mi][j][2*hh+1] - mu)*rs + nb[col + 1];
                uint32_t h, l; hilo2(x, y, h, l);
                *(uint32_t*)((__nv_bfloat16*)g_hEhi + (size_t)row*128 + col) = h;
                *(uint32_t*)((__nv_bfloat16*)g_hElo + (size_t)row*128 + col) = l;
            }
        }
}

// ==================== k_attn (fp32): softmax, attend*Vh, @Wo, residual+LN ====
__device__ __forceinline__ float2 ffma2(float2 d, float2 a, float2 b) {
    unsigned long long du = *reinterpret_cast<unsigned long long*>(&d);
    unsigned long long au = *reinterpret_cast<unsigned long long*>(&a);
    unsigned long long bu = *reinterpret_cast<unsigned long long*>(&b);
    asm("fma.rn.f32x2 %0, %1, %2, %0;" : "+l"(du) : "l"(au), "l"(bu));
    return *reinterpret_cast<float2*>(&du);
}
__device__ __forceinline__ void stage_mat128(float* ws, const float* __restrict__ W,
                                             int t, int nthreads) {
    for (int i = t; i < (128*128)/4; i += nthreads)
        reinterpret_cast<float4*>(ws)[i] = reinterpret_cast<const float4*>(W)[i];
}
__device__ __forceinline__ void tile_fma(const float* a_s, const float* w_s,
                                         int n0, int c0, float2 acc[4][2]) {
    #pragma unroll 8
    for (int j = 0; j < 128; ++j) {
        float2 w0 = *reinterpret_cast<const float2*>(&w_s[j*128 + c0]);
        float2 w1 = *reinterpret_cast<const float2*>(&w_s[j*128 + c0 + 2]);
        #pragma unroll
        for (int r = 0; r < 4; ++r) {
            float a = a_s[(n0 + r)*128 + j];
            float2 a2 = make_float2(a, a);
            acc[r][0] = ffma2(acc[r][0], a2, w0);
            acc[r][1] = ffma2(acc[r][1], a2, w1);
        }
    }
}

__global__ __launch_bounds__(256) void k_attn(const int* __restrict__ E_idx,
                                              const float* __restrict__ mask,
                                              const float* __restrict__ Wo,
                                              const float* __restrict__ lng,
                                              const float* __restrict__ lnb) {
    extern __shared__ float smf[];
    float* w_s = smf;
    float* a_s = smf + 128*128;
    __shared__ float att_s[32*NHD*KK];
    int t = threadIdx.x, tx = t & 31, ty = t >> 5;
    int n0 = ty*4, c0 = tx*4;
    int base = blockIdx.x*32;

    if (t < 128) {
        int nn = t >> 2, h = t & 3;
        int node = base + nn;
        int b = node / LL;
        float msel = mask[node];
        const int* eidx = &E_idx[node*KK];
        const float* lg = &g_logits[((size_t)node*NHD + h)*KK];
        float mk[KK], lv[KK];
        float mx = -3.4e38f;
        #pragma unroll
        for (int k = 0; k < KK; ++k) {
            int gi = b*LL + eidx[k];
            mk[k] = msel*mask[gi];
            lv[k] = lg[k];
            if (mk[k] > 0.f && lv[k] > mx) mx = lv[k];
        }
        float s = 0.f;
        #pragma unroll
        for (int k = 0; k < KK; ++k) {
            float e = (mk[k] > 0.f) ? __expf(lv[k] - mx) : 0.f;
            lv[k] = e; s += e;
        }
        float inv = (s > 0.f) ? (1.f/s) : 0.f;
        #pragma unroll
        for (int k = 0; k < KK; ++k)
            att_s[nn*(NHD*KK) + h*KK + k] = mk[k]*lv[k]*inv;
    }
    __syncthreads();

    #pragma unroll
    for (int r = 0; r < 4; ++r) {
        int nn = n0 + r;
        float4 u = make_float4(0.f, 0.f, 0.f, 0.f);
        const float* vh = &g_Vh[(size_t)(base + nn)*KK*128 + c0];
        const float* at = &att_s[nn*(NHD*KK) + (tx >> 3)*KK];
        #pragma unroll 6
        for (int k = 0; k < KK; ++k) {
            float a = at[k];
            float4 v = *reinterpret_cast<const float4*>(&vh[k*128]);
            u.x += a*v.x; u.y += a*v.y; u.z += a*v.z; u.w += a*v.w;
        }
        *reinterpret_cast<float4*>(&a_s[nn*128 + c0]) = u;
    }
    stage_mat128(w_s, Wo, t, 256);
    __syncthreads();

    float2 acc[4][2] = {};
    tile_fma(a_s, w_s, n0, c0, acc);

    float4 gv  = *reinterpret_cast<const float4*>(&lng[c0]);
    float4 bv2 = *reinterpret_cast<const float4*>(&lnb[c0]);
    #pragma unroll
    for (int r = 0; r < 4; ++r) {
        int node = base + n0 + r;
        float4 hv = *reinterpret_cast<const float4*>(&g_hV[node*128 + c0]);
        float x0 = hv.x + acc[r][0].x, x1 = hv.y + acc[r][0].y;
        float x2 = hv.z + acc[r][1].x, x3 = hv.w + acc[r][1].y;
        float s  = x0 + x1 + x2 + x3;
        float s2 = x0*x0 + x1*x1 + x2*x2 + x3*x3;
        #pragma unroll
        for (int o = 16; o > 0; o >>= 1) {
            s  += __shfl_xor_sync(0xffffffffu, s,  o);
            s2 += __shfl_xor_sync(0xffffffffu, s2, o);
        }
        float mu  = s*(1.f/128.f);
        float var = fmaxf((s2 - 128.f*mu*mu)*(1.f/127.f), 0.f);
        float rs  = 1.f/(sqrtf(var + EPSX) + EPSX);
        float m   = mask[node];
        float4 o4;
        o4.x = m*(gv.x*(x0 - mu)*rs + bv2.x);
        o4.y = m*(gv.y*(x1 - mu)*rs + bv2.y);
        o4.z = m*(gv.z*(x2 - mu)*rs + bv2.z);
        o4.w = m*(gv.w*(x3 - mu)*rs + bv2.w);
        *reinterpret_cast<float4*>(&g_hV[node*128 + c0]) = o4;
        uint2 h, l; hilo4(o4, h, l);
        *(uint2*)((__nv_bfloat16*)g_hVhi + (size_t)node*128 + c0) = h;
        *(uint2*)((__nv_bfloat16*)g_hVlo + (size_t)node*128 + c0) = l;
    }
}

__global__ void k_copy(float* __restrict__ out) {
    int i = blockIdx.x*blockDim.x + threadIdx.x;
    reinterpret_cast<float4*>(out)[i] = reinterpret_cast<const float4*>(g_hV)[i];
}

// =========================================================================
extern "C" void kernel_launch(void* const* d_in, const int* in_sizes, int n_in,
                              void* d_out, int out_size) {
    const float* V      = (const float*)d_in[0];
    const float* E      = (const float*)d_in[1];
    const int*   E_idx  = (const int*)  d_in[2];
    const float* mask   = (const float*)d_in[3];
    const float* Ws_w   = (const float*)d_in[4];
    const float* Ws_b   = (const float*)d_in[5];
    const float* Wt_w   = (const float*)d_in[6];
    const float* Wt_b   = (const float*)d_in[7];
    const float* Wq     = (const float*)d_in[8];
    const float* Wk1    = (const float*)d_in[9];
    const float* Wk2    = (const float*)d_in[10];
    const float* Wv     = (const float*)d_in[11];
    const float* Wo     = (const float*)d_in[12];
    const float* ln_g   = (const float*)d_in[13];
    const float* ln_b   = (const float*)d_in[14];
    const float* fc1_w  = (const float*)d_in[15];
    const float* fc1_b  = (const float*)d_in[16];
    const float* norm_g = (const float*)d_in[17];
    const float* norm_b = (const float*)d_in[18];

    const int SMA = (128*128 + 32*128)*4;
    cudaFuncSetAttribute(k_projf, cudaFuncAttributeMaxDynamicSharedMemorySize, SM_GEMM);
    cudaFuncSetAttribute(k_proj,  cudaFuncAttributeMaxDynamicSharedMemorySize, SM_GEMM);
    cudaFuncSetAttribute(k_lv,    cudaFuncAttributeMaxDynamicSharedMemorySize, SM_GEMM);
    cudaFuncSetAttribute(k_fc1,   cudaFuncAttributeMaxDynamicSharedMemorySize, SM_GEMM);
    cudaFuncSetAttribute(k_attn,  cudaFuncAttributeMaxDynamicSharedMemorySize, SMA);

    void *phV, *pQ, *phVh, *phVl, *phEh, *phEl;
    cudaGetSymbolAddress(&phV,  g_hV);
    cudaGetSymbolAddress(&pQ,   g_Q);
    cudaGetSymbolAddress(&phVh, g_hVhi);    cudaGetSymbolAddress(&phVl, g_hVlo);
    cudaGetSymbolAddress(&phEh, g_hEhi);    cudaGetSymbolAddress(&phEl, g_hElo);

    const int PGRID = 296;   // 2 CTAs/SM * 148 SMs (persistent)

    k_wconv_all<<<(23*16384 + 255)/256, 256>>>(Ws_w, Wt_w, Wq, Wk1, Wk2, Wv, fc1_w, Wo);
    // initial projections: fp32 inputs, fused hi/lo split (no fconv round trip)
    k_projf<<<128, 128, SM_GEMM>>>(V, 0, Ws_b, (float*)phV,
                                   (__nv_bfloat16*)phVh, (__nv_bfloat16*)phVl, NNODE/64);
    k_projf<<<PGRID, 128, SM_GEMM>>>(E, 1, Wt_b, nullptr,
                                     (__nv_bfloat16*)phEh, (__nv_bfloat16*)phEl, NE/64);

    for (int i = 0; i < NLAY; ++i) {
        k_proj<<<128, 128, SM_GEMM>>>((const uint4*)phVh, (const uint4*)phVl,
                                      2 + i, nullptr, (float*)pQ, nullptr, nullptr, NNODE/64);
        k_lv<<<NE/64, 128, SM_GEMM>>>(E_idx, 5 + i, 8 + i, 11 + 2*i, 12 + 2*i);
        k_attn<<<NNODE/32, 256, SMA>>>(E_idx, mask, Wo + i*128*128,
                                       ln_g + i*128, ln_b + i*128);
        k_fc1<<<NE/64, 128, SM_GEMM>>>(E_idx, fc1_b, norm_g, norm_b);
    }

    k_copy<<<(NNODE*128/4)/256, 256>>>((float*)d_out);
    (void)in_sizes; (void)n_in; (void)out_size;
}

// round 16
// speedup vs baseline: 1.2675x; 1.0183x over previous
#include <cuda_runtime.h>
#include <cuda_bf16.h>
#include <stdint.h>
#include <math.h>

#define BB 4
#define LL 2048
#define KK 30
#define NHD 4
#define NLAY 3
#define NNODE (BB*LL)        /* 8192   */
#define NE (NNODE*KK)        /* 245760 */
#define EPSX 1e-6f

// ==================== device scratch (static, no allocation) ====================
__device__ float g_hV[NNODE*128];
__device__ float g_Q[NNODE*128];
__device__ __nv_bfloat16 g_Vhb[(size_t)NE*128];               // Vh, bf16 (63 MB)
__device__ float g_logits[(size_t)NNODE*NHD*KK];
__device__ __nv_bfloat16 g_wbhi[23*16384], g_wblo[23*16384];  // weights [n][k] bf16
__device__ uint4 g_hVhi[NNODE*16], g_hVlo[NNODE*16];
__device__ uint4 g_hEhi[(size_t)NE*16],  g_hElo[(size_t)NE*16];

// ==================== helpers ====================
__device__ __forceinline__ uint32_t smem_u32(const void* p) {
    uint32_t a;
    asm("{ .reg .u64 tmp; cvta.to.shared.u64 tmp, %1; cvt.u32.u64 %0, tmp; }"
        : "=r"(a) : "l"(p));
    return a;
}
__device__ __forceinline__ void ldsm4(uint32_t r[4], uint32_t addr) {
    asm volatile("ldmatrix.sync.aligned.m8n8.x4.shared.b16 {%0,%1,%2,%3}, [%4];"
        : "=r"(r[0]), "=r"(r[1]), "=r"(r[2]), "=r"(r[3]) : "r"(addr));
}
__device__ __forceinline__ void mma16816(float c[4], const uint32_t a[4], const uint32_t b[2]) {
    asm volatile("mma.sync.aligned.m16n8k16.row.col.f32.bf16.bf16.f32 "
        "{%0,%1,%2,%3}, {%4,%5,%6,%7}, {%8,%9}, {%0,%1,%2,%3};"
        : "+f"(c[0]), "+f"(c[1]), "+f"(c[2]), "+f"(c[3])
        : "r"(a[0]), "r"(a[1]), "r"(a[2]), "r"(a[3]), "r"(b[0]), "r"(b[1]));
}
__device__ __forceinline__ void hilo2(float x, float y, uint32_t& h, uint32_t& l) {
    __nv_bfloat16 hx = __float2bfloat16_rn(x), hy = __float2bfloat16_rn(y);
    __nv_bfloat16 lx = __float2bfloat16_rn(x - __bfloat162float(hx));
    __nv_bfloat16 ly = __float2bfloat16_rn(y - __bfloat162float(hy));
    h = (uint32_t)__bfloat16_as_ushort(hx) | ((uint32_t)__bfloat16_as_ushort(hy) << 16);
    l = (uint32_t)__bfloat16_as_ushort(lx) | ((uint32_t)__bfloat16_as_ushort(ly) << 16);
}
__device__ __forceinline__ void hilo4(float4 v, uint2& h, uint2& l) {
    hilo2(v.x, v.y, h.x, l.x);
    hilo2(v.z, v.w, h.y, l.y);
}
__device__ __forceinline__ void cpa16(uint32_t dst, const void* src) {
    asm volatile("cp.async.cg.shared.global [%0], [%1], 16;" :: "r"(dst), "l"(src) : "memory");
}
#define CP_COMMIT() asm volatile("cp.async.commit_group;" ::: "memory")
#define CP_WAIT0()  asm volatile("cp.async.wait_group 0;" ::: "memory")

// ==================== smem layout ====================
#define A1B 17408                 /* 64*272                 */
#define W1B 34816                 /* 128*272                */
#define OFF_A  0                  /* A hi @0, A lo @A1B     */
#define OFF_W  (2*A1B)            /* W hi @OFF_W, lo +W1B   */
#define SM_GEMM (2*A1B + 2*W1B)   /* 104448 -> 2 CTAs/SM    */

// 128-thread stagers
__device__ __forceinline__ void stage_a_cp(uint32_t sb, const uint4* ghi,
                                           const uint4* glo, const int* grow,
                                           long base, int t) {
    #pragma unroll
    for (int i = 0; i < 8; ++i) {
        int idx = t + 128*i;              // 1024 chunks = 64 rows * 16
        int row = idx >> 4, c = idx & 15;
        long gr = grow ? (long)grow[row] : (base + row);
        uint32_t d = (uint32_t)(row*272 + c*16);
        cpa16(sb + OFF_A + d,       ghi + gr*16 + c);
        cpa16(sb + OFF_A + A1B + d, glo + gr*16 + c);
    }
}
// fp32 source: LDG float4, split to bf16 hi/lo in regs, STS both halves
__device__ __forceinline__ void stage_a_f32v(char* smc, const float4* gsrc,
                                             long base, int t) {
    #pragma unroll
    for (int i = 0; i < 16; ++i) {
        int idx = t + 128*i;              // 2048 float4 chunks = 64 rows * 32
        int row = idx >> 5, c = idx & 31;
        float4 v = gsrc[(base + row)*32 + c];
        uint2 h, l; hilo4(v, h, l);
        uint32_t d = (uint32_t)(row*272 + c*8);
        *(uint2*)(smc + OFF_A + d)       = h;
        *(uint2*)(smc + OFF_A + A1B + d) = l;
    }
}
__device__ __forceinline__ void stage_w_cp(uint32_t sb, int block, int t) {
    const uint4* sh = (const uint4*)(g_wbhi + (size_t)block*16384);
    const uint4* sl = (const uint4*)(g_wblo + (size_t)block*16384);
    #pragma unroll
    for (int i = 0; i < 16; ++i) {
        int idx = t + 128*i;              // 2048 chunks = 128 rows * 16
        int row = idx >> 4, c = idx & 15;
        uint32_t d = (uint32_t)(row*272 + c*16);
        cpa16(sb + OFF_W + d,       sh + idx);
        cpa16(sb + OFF_W + W1B + d, sl + idx);
    }
}

// 3-term split GEMM on 64x128 tile; 4 warps, warp tile 32x64. Term-major order.
__device__ __forceinline__ void gemm3(uint32_t sb, int lane, int wr, int wc,
                                      float acc[2][8][4]) {
    uint32_t arow = (uint32_t)(32*wr + (lane & 15));
    uint32_t acol = (uint32_t)((lane >> 4) << 3);
    uint32_t brow = (uint32_t)(64*wc + (lane & 7) + ((lane >> 4) << 3));
    uint32_t bcol = (uint32_t)(((lane >> 3) & 1) << 3);
    #pragma unroll 2
    for (int ks = 0; ks < 8; ++ks) {
        uint32_t k0 = (uint32_t)(ks*16);
        uint32_t ah[2][4], al[2][4];
        #pragma unroll
        for (int mi = 0; mi < 2; ++mi) {
            uint32_t off = ((arow + 16u*mi)*136u + k0 + acol)*2u;
            ldsm4(ah[mi], sb + OFF_A + off);
            ldsm4(al[mi], sb + OFF_A + A1B + off);
        }
        uint32_t bh[8][2], bl[8][2];
        #pragma unroll
        for (int jp = 0; jp < 4; ++jp) {
            uint32_t off = ((brow + 16u*jp)*136u + k0 + bcol)*2u;
            uint32_t r[4];
            ldsm4(r, sb + OFF_W + off);
            bh[2*jp][0] = r[0]; bh[2*jp][1] = r[1];
            bh[2*jp+1][0] = r[2]; bh[2*jp+1][1] = r[3];
            ldsm4(r, sb + OFF_W + W1B + off);
            bl[2*jp][0] = r[0]; bl[2*jp][1] = r[1];
            bl[2*jp+1][0] = r[2]; bl[2*jp+1][1] = r[3];
        }
        #pragma unroll
        for (int mi = 0; mi < 2; ++mi)
            #pragma unroll
            for (int j = 0; j < 8; ++j)
                mma16816(acc[mi][j], ah[mi], bh[j]);
        #pragma unroll
        for (int mi = 0; mi < 2; ++mi)
            #pragma unroll
            for (int j = 0; j < 8; ++j)
                mma16816(acc[mi][j], ah[mi], bl[j]);
        #pragma unroll
        for (int mi = 0; mi < 2; ++mi)
            #pragma unroll
            for (int j = 0; j < 8; ++j)
                mma16816(acc[mi][j], al[mi], bh[j]);
    }
}

// ==================== weight conversion ====================
// blocks: 0 Ws, 1 Wt, 2-4 Wq, 5-7 Wk1, 8-10 Wk2, 11-16 Wv, 17-19 fc1, 20-22 Wo
__global__ void k_wconv_all(const float* __restrict__ Ws, const float* __restrict__ Wt,
                            const float* __restrict__ Wq, const float* __restrict__ Wk1,
                            const float* __restrict__ Wk2, const float* __restrict__ Wv,
                            const float* __restrict__ fc1, const float* __restrict__ Wo) {
    int i = blockIdx.x*blockDim.x + threadIdx.x;
    if (i >= 23*16384) return;
    int blk = i >> 14, r = i & 16383, n = r >> 7, k = r & 127;
    const float* src; int sub;
    if (blk == 0)       { src = Ws;  sub = 0; }
    else if (blk == 1)  { src = Wt;  sub = 0; }
    else if (blk < 5)   { src = Wq;  sub = blk - 2; }
    else if (blk < 8)   { src = Wk1; sub = blk - 5; }
    else if (blk < 11)  { src = Wk2; sub = blk - 8; }
    else if (blk < 17)  { src = Wv;  sub = blk - 11; }
    else if (blk < 20)  { src = fc1; sub = blk - 17; }
    else                { src = Wo;  sub = blk - 20; }
    float v = src[(size_t)sub*16384 + k*128 + n];
    __nv_bfloat16 h = __float2bfloat16_rn(v);
    __nv_bfloat16 l = __float2bfloat16_rn(v - __bfloat162float(h));
    size_t e = (size_t)blk*16384 + n*128 + k;
    g_wbhi[e] = h; g_wblo[e] = l;
}

// ==================== k_projf: PERSISTENT, fp32 input, fused convert ====
__global__ __launch_bounds__(128, 2) void k_projf(const float* __restrict__ act,
                                                  int wblock,
                                                  const float* __restrict__ bias,
                                                  float* __restrict__ outf,
                                                  __nv_bfloat16* __restrict__ outhi,
                                                  __nv_bfloat16* __restrict__ outlo,
                                                  int ntiles) {
    extern __shared__ char smc[];
    uint32_t sb = smem_u32(smc);
    int t = threadIdx.x, lane = t & 31, wid = t >> 5, wr = wid & 1, wc = wid >> 1;
    const float4* gsrc = (const float4*)act;

    stage_w_cp(sb, wblock, t);
    CP_COMMIT();
    int tile = blockIdx.x;
    if (tile < ntiles)
        stage_a_f32v(smc, gsrc, (long)tile*64, t);
    CP_WAIT0();
    __syncthreads();

    for (; tile < ntiles; tile += gridDim.x) {
        float acc[2][8][4] = {};
        gemm3(sb, lane, wr, wc, acc);
        __syncthreads();

        int nxt = tile + gridDim.x;
        if (nxt < ntiles)
            stage_a_f32v(smc, gsrc, (long)nxt*64, t);

        long base = (long)tile*64;
        #pragma unroll
        for (int mi = 0; mi < 2; ++mi)
            #pragma unroll
            for (int hh = 0; hh < 2; ++hh) {
                long row = base + 32*wr + 16*mi + 8*hh + (lane >> 2);
                #pragma unroll
                for (int j = 0; j < 8; ++j) {
                    int col = 64*wc + 8*j + 2*(lane & 3);
                    float x = acc[mi][j][2*hh], y = acc[mi][j][2*hh + 1];
                    if (bias) { x += bias[col]; y += bias[col + 1]; }
                    if (outf) *(float2*)(outf + row*128 + col) = make_float2(x, y);
                    if (outhi) {
                        uint32_t h, l; hilo2(x, y, h, l);
                        *(uint32_t*)(outhi + row*128 + col) = h;
                        *(uint32_t*)(outlo + row*128 + col) = l;
                    }
                }
            }
        __syncthreads();
    }
}

// ==================== k_proj: PERSISTENT, bf16-pair input ====
__global__ __launch_bounds__(128, 2) void k_proj(const uint4* __restrict__ ahi,
                                                 const uint4* __restrict__ alo,
                                                 int wblock,
                                                 const float* __restrict__ bias,
                                                 float* __restrict__ outf,
                                                 __nv_bfloat16* __restrict__ outhi,
                                                 __nv_bfloat16* __restrict__ outlo,
                                                 int ntiles) {
    extern __shared__ char smc[];
    uint32_t sb = smem_u32(smc);
    int t = threadIdx.x, lane = t & 31, wid = t >> 5, wr = wid & 1, wc = wid >> 1;

    stage_w_cp(sb, wblock, t);
    int tile = blockIdx.x;
    if (tile < ntiles)
        stage_a_cp(sb, ahi, alo, nullptr, (long)tile*64, t);
    CP_COMMIT(); CP_WAIT0();
    __syncthreads();

    for (; tile < ntiles; tile += gridDim.x) {
        float acc[2][8][4] = {};
        gemm3(sb, lane, wr, wc, acc);
        __syncthreads();

        int nxt = tile + gridDim.x;
        if (nxt < ntiles) {
            stage_a_cp(sb, ahi, alo, nullptr, (long)nxt*64, t);
            CP_COMMIT();
        }

        long base = (long)tile*64;
        #pragma unroll
        for (int mi = 0; mi < 2; ++mi)
            #pragma unroll
            for (int hh = 0; hh < 2; ++hh) {
                long row = base + 32*wr + 16*mi + 8*hh + (lane >> 2);
                #pragma unroll
                for (int j = 0; j < 8; ++j) {
                    int col = 64*wc + 8*j + 2*(lane & 3);
                    float x = acc[mi][j][2*hh], y = acc[mi][j][2*hh + 1];
                    if (bias) { x += bias[col]; y += bias[col + 1]; }
                    if (outf) *(float2*)(outf + row*128 + col) = make_float2(x, y);
                    if (outhi) {
                        uint32_t h, l; hilo2(x, y, h, l);
                        *(uint32_t*)(outhi + row*128 + col) = h;
                        *(uint32_t*)(outlo + row*128 + col) = l;
                    }
                }
            }
        CP_WAIT0(); __syncthreads();
    }
}

// ==================== k_lv: K1, K2 -> logits; Vh (bf16). 64 rows/CTA ============
__global__ __launch_bounds__(128, 2) void k_lv(const int* __restrict__ E_idx,
                                               int bk1, int bk2, int bv0, int bv1) {
    extern __shared__ char smc[];
    __shared__ int grow[64];
    uint32_t sb = smem_u32(smc);
    int t = threadIdx.x, lane = t & 31, wid = t >> 5, wr = wid & 1, wc = wid >> 1;
    long base = (long)blockIdx.x*64;

    if (t < 64) {
        long e = base + t;
        grow[t] = (int)(e/(LL*KK))*LL + E_idx[e];
    }
    stage_a_cp(sb, g_hEhi, g_hElo, nullptr, base, t);
    stage_w_cp(sb, bk1, t);
    CP_COMMIT(); CP_WAIT0();
    __syncthreads();

    float acc1[2][8][4] = {};
    gemm3(sb, lane, wr, wc, acc1);                 // K1 = hE @ Wk1
    __syncthreads();

    stage_a_cp(sb, g_hVhi, g_hVlo, grow, 0, t);    // A <- gathered hV
    stage_w_cp(sb, bk2, t);
    CP_COMMIT(); CP_WAIT0();
    __syncthreads();

    float acc2[2][8][4] = {};
    gemm3(sb, lane, wr, wc, acc2);                 // K2 = hKV @ Wk2
    __syncthreads();

    stage_w_cp(sb, bv1, t);
    CP_COMMIT();

    #pragma unroll
    for (int mi = 0; mi < 2; ++mi)
        #pragma unroll
        for (int hh = 0; hh < 2; ++hh) {
            int r = 32*wr + 16*mi + 8*hh + (lane >> 2);
            long e = base + r;
            int node = (int)(e / KK), kk = (int)(e - (long)node*KK);
            const float* qrow = g_Q + (size_t)node*128;
            float s0 = 0.f, s1 = 0.f;
            #pragma unroll
            for (int j = 0; j < 8; ++j) {
                int col = 64*wc + 8*j + 2*(lane & 3);
                float2 q = *(const float2*)(qrow + col);
                float p = q.x*acc1[mi][j][2*hh]  *acc2[mi][j][2*hh]
                        + q.y*acc1[mi][j][2*hh+1]*acc2[mi][j][2*hh+1];
                if (j < 4) s0 += p; else s1 += p;
            }
            s0 += __shfl_xor_sync(0xffffffffu, s0, 1);
            s0 += __shfl_xor_sync(0xffffffffu, s0, 2);
            s1 += __shfl_xor_sync(0xffffffffu, s1, 1);
            s1 += __shfl_xor_sync(0xffffffffu, s1, 2);
            if ((lane & 3) == 0) {
                g_logits[((size_t)node*NHD + 2*wc    )*KK + kk] = s0*(1.f/32.f);
                g_logits[((size_t)node*NHD + 2*wc + 1)*KK + kk] = s1*(1.f/32.f);
            }
        }
    CP_WAIT0(); __syncthreads();

    float accv[2][8][4] = {};
    gemm3(sb, lane, wr, wc, accv);                 // Vh = hKV @ Wv1
    __syncthreads();

    stage_a_cp(sb, g_hEhi, g_hElo, nullptr, base, t);
    stage_w_cp(sb, bv0, t);
    CP_COMMIT(); CP_WAIT0();
    __syncthreads();

    gemm3(sb, lane, wr, wc, accv);                 // Vh += hE @ Wv0

    // store Vh as bf16 (halves traffic vs fp32)
    #pragma unroll
    for (int mi = 0; mi < 2; ++mi)
        #pragma unroll
        for (int hh = 0; hh < 2; ++hh) {
            long row = base + 32*wr + 16*mi + 8*hh + (lane >> 2);
            #pragma unroll
            for (int j = 0; j < 8; ++j) {
                int col = 64*wc + 8*j + 2*(lane & 3);
                __nv_bfloat162 p = __floats2bfloat162_rn(accv[mi][j][2*hh],
                                                         accv[mi][j][2*hh+1]);
                *(__nv_bfloat162*)(g_Vhb + (size_t)row*128 + col) = p;
            }
        }
}

// ==================== k_fc1: h_E = LN(relu([hE, hKV, hVself] @ fc1 + b)) ====
__global__ __launch_bounds__(128, 2) void k_fc1(const int* __restrict__ E_idx,
                                                const float* __restrict__ fc1b,
                                                const float* __restrict__ ng,
                                                const float* __restrict__ nb) {
    extern __shared__ char smc[];
    __shared__ int grow[64], grow2[64];
    __shared__ float reds[128], reds2[128];
    uint32_t sb = smem_u32(smc);
    int t = threadIdx.x, lane = t & 31, wid = t >> 5, wr = wid & 1, wc = wid >> 1;
    long base = (long)blockIdx.x*64;

    if (t < 64) {
        long e = base + t;
        grow[t]  = (int)(e/(LL*KK))*LL + E_idx[e];
        grow2[t] = (int)(e / KK);
    }
    stage_a_cp(sb, g_hEhi, g_hElo, nullptr, base, t);
    stage_w_cp(sb, 17, t);
    CP_COMMIT(); CP_WAIT0();
    __syncthreads();

    float acc[2][8][4] = {};
    gemm3(sb, lane, wr, wc, acc);
    __syncthreads();

    stage_a_cp(sb, g_hVhi, g_hVlo, grow, 0, t);
    stage_w_cp(sb, 18, t);
    CP_COMMIT(); CP_WAIT0();
    __syncthreads();

    gemm3(sb, lane, wr, wc, acc);
    __syncthreads();

    stage_a_cp(sb, g_hVhi, g_hVlo, grow2, 0, t);
    stage_w_cp(sb, 19, t);
    CP_COMMIT(); CP_WAIT0();
    __syncthreads();

    gemm3(sb, lane, wr, wc, acc);

    #pragma unroll
    for (int mi = 0; mi < 2; ++mi)
        #pragma unroll
        for (int hh = 0; hh < 2; ++hh) {
            int r = 32*wr + 16*mi + 8*hh + (lane >> 2);
            float s = 0.f, s2 = 0.f;
            #pragma unroll
            for (int j = 0; j < 8; ++j) {
                int col = 64*wc + 8*j + 2*(lane & 3);
                float x = fmaxf(acc[mi][j][2*hh]   + fc1b[col],     0.f);
                float y = fmaxf(acc[mi][j][2*hh+1] + fc1b[col + 1], 0.f);
                acc[mi][j][2*hh] = x; acc[mi][j][2*hh+1] = y;
                s += x + y; s2 += x*x + y*y;
            }
            s  += __shfl_xor_sync(0xffffffffu, s, 1);
            s  += __shfl_xor_sync(0xffffffffu, s, 2);
            s2 += __shfl_xor_sync(0xffffffffu, s2, 1);
            s2 += __shfl_xor_sync(0xffffffffu, s2, 2);
            if ((lane & 3) == 0) { reds[r*2 + wc] = s; reds2[r*2 + wc] = s2; }
        }
    __syncthreads();

    #pragma unroll
    for (int mi = 0; mi < 2; ++mi)
        #pragma unroll
        for (int hh = 0; hh < 2; ++hh) {
            int r = 32*wr + 16*mi + 8*hh + (lane >> 2);
            float s  = reds[r*2] + reds[r*2 + 1];
            float s2 = reds2[r*2] + reds2[r*2 + 1];
            float mu  = s*(1.f/128.f);
            float var = fmaxf((s2 - 128.f*mu*mu)*(1.f/127.f), 0.f);
            float rs  = 1.f/(sqrtf(var + EPSX) + EPSX);
            long row = base + r;
            #pragma unroll
            for (int j = 0; j < 8; ++j) {
                int col = 64*wc + 8*j + 2*(lane & 3);
                float x = ng[col    ]*(acc[mi][j][2*hh]   - mu)*rs + nb[col];
                float y = ng[col + 1]*(acc[mi][j][2*hh+1] - mu)*rs + nb[col + 1];
                uint32_t h, l; hilo2(x, y, h, l);
                *(uint32_t*)((__nv_bfloat16*)g_hEhi + (size_t)row*128 + col) = h;
                *(uint32_t*)((__nv_bfloat16*)g_hElo + (size_t)row*128 + col) = l;
            }
        }
}

// ==================== k_attn (fp32): softmax, attend*Vh(bf16), @Wo, residual+LN ====
__device__ __forceinline__ float2 ffma2(float2 d, float2 a, float2 b) {
    unsigned long long du = *reinterpret_cast<unsigned long long*>(&d);
    unsigned long long au = *reinterpret_cast<unsigned long long*>(&a);
    unsigned long long bu = *reinterpret_cast<unsigned long long*>(&b);
    asm("fma.rn.f32x2 %0, %1, %2, %0;" : "+l"(du) : "l"(au), "l"(bu));
    return *reinterpret_cast<float2*>(&du);
}
__device__ __forceinline__ void stage_mat128(float* ws, const float* __restrict__ W,
                                             int t, int nthreads) {
    for (int i = t; i < (128*128)/4; i += nthreads)
        reinterpret_cast<float4*>(ws)[i] = reinterpret_cast<const float4*>(W)[i];
}
__device__ __forceinline__ void tile_fma(const float* a_s, const float* w_s,
                                         int n0, int c0, float2 acc[4][2]) {
    #pragma unroll 8
    for (int j = 0; j < 128; ++j) {
        float2 w0 = *reinterpret_cast<const float2*>(&w_s[j*128 + c0]);
        float2 w1 = *reinterpret_cast<const float2*>(&w_s[j*128 + c0 + 2]);
        #pragma unroll
        for (int r = 0; r < 4; ++r) {
            float a = a_s[(n0 + r)*128 + j];
            float2 a2 = make_float2(a, a);
            acc[r][0] = ffma2(acc[r][0], a2, w0);
            acc[r][1] = ffma2(acc[r][1], a2, w1);
        }
    }
}

__global__ __launch_bounds__(256) void k_attn(const int* __restrict__ E_idx,
                                              const float* __restrict__ mask,
                                              const float* __restrict__ Wo,
                                              const float* __restrict__ lng,
                                              const float* __restrict__ lnb) {
    extern __shared__ float smf[];
    float* w_s = smf;
    float* a_s = smf + 128*128;
    __shared__ float att_s[32*NHD*KK];
    int t = threadIdx.x, tx = t & 31, ty = t >> 5;
    int n0 = ty*4, c0 = tx*4;
    int base = blockIdx.x*32;

    if (t < 128) {
        int nn = t >> 2, h = t & 3;
        int node = base + nn;
        int b = node / LL;
        float msel = mask[node];
        const int* eidx = &E_idx[node*KK];
        const float* lg = &g_logits[((size_t)node*NHD + h)*KK];
        float mk[KK], lv[KK];
        float mx = -3.4e38f;
        #pragma unroll
        for (int k = 0; k < KK; ++k) {
            int gi = b*LL + eidx[k];
            mk[k] = msel*mask[gi];
            lv[k] = lg[k];
            if (mk[k] > 0.f && lv[k] > mx) mx = lv[k];
        }
        float s = 0.f;
        #pragma unroll
        for (int k = 0; k < KK; ++k) {
            float e = (mk[k] > 0.f) ? __expf(lv[k] - mx) : 0.f;
            lv[k] = e; s += e;
        }
        float inv = (s > 0.f) ? (1.f/s) : 0.f;
        #pragma unroll
        for (int k = 0; k < KK; ++k)
            att_s[nn*(NHD*KK) + h*KK + k] = mk[k]*lv[k]*inv;
    }
    __syncthreads();

    #pragma unroll
    for (int r = 0; r < 4; ++r) {
        int nn = n0 + r;
        float4 u = make_float4(0.f, 0.f, 0.f, 0.f);
        const __nv_bfloat16* vh = g_Vhb + (size_t)(base + nn)*KK*128 + c0;
        const float* at = &att_s[nn*(NHD*KK) + (tx >> 3)*KK];
        #pragma unroll 6
        for (int k = 0; k < KK; ++k) {
            float a = at[k];
            uint2 p = *reinterpret_cast<const uint2*>(vh + k*128);
            float2 f0 = __bfloat1622float2(*reinterpret_cast<__nv_bfloat162*>(&p.x));
            float2 f1 = __bfloat1622float2(*reinterpret_cast<__nv_bfloat162*>(&p.y));
            u.x += a*f0.x; u.y += a*f0.y; u.z += a*f1.x; u.w += a*f1.y;
        }
        *reinterpret_cast<float4*>(&a_s[nn*128 + c0]) = u;
    }
    stage_mat128(w_s, Wo, t, 256);
    __syncthreads();

    float2 acc[4][2] = {};
    tile_fma(a_s, w_s, n0, c0, acc);

    float4 gv  = *reinterpret_cast<const float4*>(&lng[c0]);
    float4 bv2 = *reinterpret_cast<const float4*>(&lnb[c0]);
    #pragma unroll
    for (int r = 0; r < 4; ++r) {
        int node = base + n0 + r;
        float4 hv = *reinterpret_cast<const float4*>(&g_hV[node*128 + c0]);
        float x0 = hv.x + acc[r][0].x, x1 = hv.y + acc[r][0].y;
        float x2 = hv.z + acc[r][1].x, x3 = hv.w + acc[r][1].y;
        float s  = x0 + x1 + x2 + x3;
        float s2 = x0*x0 + x1*x1 + x2*x2 + x3*x3;
        #pragma unroll
        for (int o = 16; o > 0; o >>= 1) {
            s  += __shfl_xor_sync(0xffffffffu, s,  o);
            s2 += __shfl_xor_sync(0xffffffffu, s2, o);
        }
        float mu  = s*(1.f/128.f);
        float var = fmaxf((s2 - 128.f*mu*mu)*(1.f/127.f), 0.f);
        float rs  = 1.f/(sqrtf(var + EPSX) + EPSX);
        float m   = mask[node];
        float4 o4;
        o4.x = m*(gv.x*(x0 - mu)*rs + bv2.x);
        o4.y = m*(gv.y*(x1 - mu)*rs + bv2.y);
        o4.z = m*(gv.z*(x2 - mu)*rs + bv2.z);
        o4.w = m*(gv.w*(x3 - mu)*rs + bv2.w);
        *reinterpret_cast<float4*>(&g_hV[node*128 + c0]) = o4;
        uint2 h, l; hilo4(o4, h, l);
        *(uint2*)((__nv_bfloat16*)g_hVhi + (size_t)node*128 + c0) = h;
        *(uint2*)((__nv_bfloat16*)g_hVlo + (size_t)node*128 + c0) = l;
    }
}

__global__ void k_copy(float* __restrict__ out) {
    int i = blockIdx.x*blockDim.x + threadIdx.x;
    reinterpret_cast<float4*>(out)[i] = reinterpret_cast<const float4*>(g_hV)[i];
}

// =========================================================================
extern "C" void kernel_launch(void* const* d_in, const int* in_sizes, int n_in,
                              void* d_out, int out_size) {
    const float* V      = (const float*)d_in[0];
    const float* E      = (const float*)d_in[1];
    const int*   E_idx  = (const int*)  d_in[2];
    const float* mask   = (const float*)d_in[3];
    const float* Ws_w   = (const float*)d_in[4];
    const float* Ws_b   = (const float*)d_in[5];
    const float* Wt_w   = (const float*)d_in[6];
    const float* Wt_b   = (const float*)d_in[7];
    const float* Wq     = (const float*)d_in[8];
    const float* Wk1    = (const float*)d_in[9];
    const float* Wk2    = (const float*)d_in[10];
    const float* Wv     = (const float*)d_in[11];
    const float* Wo     = (const float*)d_in[12];
    const float* ln_g   = (const float*)d_in[13];
    const float* ln_b   = (const float*)d_in[14];
    const float* fc1_w  = (const float*)d_in[15];
    const float* fc1_b  = (const float*)d_in[16];
    const float* norm_g = (const float*)d_in[17];
    const float* norm_b = (const float*)d_in[18];

    const int SMA = (128*128 + 32*128)*4;
    cudaFuncSetAttribute(k_projf, cudaFuncAttributeMaxDynamicSharedMemorySize, SM_GEMM);
    cudaFuncSetAttribute(k_proj,  cudaFuncAttributeMaxDynamicSharedMemorySize, SM_GEMM);
    cudaFuncSetAttribute(k_lv,    cudaFuncAttributeMaxDynamicSharedMemorySize, SM_GEMM);
    cudaFuncSetAttribute(k_fc1,   cudaFuncAttributeMaxDynamicSharedMemorySize, SM_GEMM);
    cudaFuncSetAttribute(k_attn,  cudaFuncAttributeMaxDynamicSharedMemorySize, SMA);

    void *phV, *pQ, *phVh, *phVl, *phEh, *phEl;
    cudaGetSymbolAddress(&phV,  g_hV);
    cudaGetSymbolAddress(&pQ,   g_Q);
    cudaGetSymbolAddress(&phVh, g_hVhi);    cudaGetSymbolAddress(&phVl, g_hVlo);
    cudaGetSymbolAddress(&phEh, g_hEhi);    cudaGetSymbolAddress(&phEl, g_hElo);

    const int PGRID = 296;   // 2 CTAs/SM * 148 SMs (persistent)

    k_wconv_all<<<(23*16384 + 255)/256, 256>>>(Ws_w, Wt_w, Wq, Wk1, Wk2, Wv, fc1_w, Wo);
    k_projf<<<128, 128, SM_GEMM>>>(V, 0, Ws_b, (float*)phV,
                                   (__nv_bfloat16*)phVh, (__nv_bfloat16*)phVl, NNODE/64);
    k_projf<<<PGRID, 128, SM_GEMM>>>(E, 1, Wt_b, nullptr,
                                     (__nv_bfloat16*)phEh, (__nv_bfloat16*)phEl, NE/64);

    for (int i = 0; i < NLAY; ++i) {
        k_proj<<<128, 128, SM_GEMM>>>((const uint4*)phVh, (const uint4*)phVl,
                                      2 + i, nullptr, (float*)pQ, nullptr, nullptr, NNODE/64);
        k_lv<<<NE/64, 128, SM_GEMM>>>(E_idx, 5 + i, 8 + i, 11 + 2*i, 12 + 2*i);
        k_attn<<<NNODE/32, 256, SMA>>>(E_idx, mask, Wo + i*128*128,
                                       ln_g + i*128, ln_b + i*128);
        k_fc1<<<NE/64, 128, SM_GEMM>>>(E_idx, fc1_b, norm_g, norm_b);
    }

    k_copy<<<(NNODE*128/4)/256, 256>>>((float*)d_out);
    (void)in_sizes; (void)n_in; (void)out_size;
}